// round 1
// baseline (speedup 1.0000x reference)
#include <cuda_runtime.h>
#include <cstdint>

// Problem shape (fixed by the dataset): N=100000 nodes, E=1600000 edges,
// D = H*C = 128, H=4 heads, C=32. Self-loops appended: ET = E + N.
#define N_MAX  100000
#define ET_MAX 1700000
#define NEG_SLOPE 0.2f

// ---------------- scratch (device globals; no allocation APIs allowed) ------
__device__ int    g_is64;                 // edge_index dtype flag (1 = int64)
__device__ float4 g_h[N_MAX * 32];        // transformed features h = x@W, [N,128]
__device__ float4 g_as[N_MAX];            // alpha_src per node [N,4]
__device__ float4 g_ad[N_MAX];            // alpha_dst per node [N,4]
__device__ float4 g_m[N_MAX];             // segment max per (dst,head)
__device__ float4 g_den[N_MAX];           // segment sum of exp per (dst,head)
__device__ float4 g_eexp[ET_MAX];         // exp(e - m) per edge [ET,4]
__device__ float4 g_out[N_MAX * 32];      // layer-1 output / layer-2 input

// ---------------- small helpers ---------------------------------------------
__device__ __forceinline__ float lrelu(float x) { return x > 0.f ? x : NEG_SLOPE * x; }

// fp32 atomic max via int/uint ordering trick (handles mixed signs, init -inf)
__device__ __forceinline__ void atomicMaxF(float* addr, float v) {
    if (v >= 0.f) atomicMax((int*)addr, __float_as_int(v));
    else          atomicMin((unsigned int*)addr, __float_as_uint(v));
}

// vectorized no-return reduction: 16B per op instead of 4x scalar RED
__device__ __forceinline__ void red_add_v4(float4* addr, float4 v) {
    asm volatile(
        "{ .reg .u64 p; cvta.to.global.u64 p, %0;\n"
        "  red.global.add.v4.f32 [p], {%1, %2, %3, %4}; }\n"
        :: "l"(addr), "f"(v.x), "f"(v.y), "f"(v.z), "f"(v.w) : "memory");
}

// edge fetch with self-loop virtualization and dtype dispatch
__device__ __forceinline__ int2 get_edge(const void* ei, int e, int E) {
    if (e >= E) { int v = e - E; return make_int2(v, v); }
    if (g_is64) {
        const long long* p = (const long long*)ei;
        return make_int2((int)p[e], (int)p[E + e]);
    } else {
        const int* p = (const int*)ei;
        return make_int2(p[e], p[E + e]);
    }
}

// ---------------- kernels ----------------------------------------------------

// detect int64 vs int32 edge_index: int64 little-endian => odd int32 words are 0
__global__ void k_detect(const int* __restrict__ p) {
    if (threadIdx.x == 0 && blockIdx.x == 0) {
        int is64 = 1;
        for (int i = 1; i < 128; i += 2)
            if (p[i] != 0) { is64 = 0; break; }
        g_is64 = is64;
    }
}

// h = A @ W  (A: [N,128], W: [128,128]) with fused alpha_src/alpha_dst epilogue.
// Block = 256 threads / 8 warps, 64 rows per block, W staged in smem in two
// 64x128 halves (32KB). Each thread: 8 rows x 4 cols (stride-32) accumulators.
__global__ __launch_bounds__(256)
void k_gemm(const float* __restrict__ A, const float* __restrict__ W,
            const float* __restrict__ a_s, const float* __restrict__ a_d, int Nn) {
    __shared__ float Ws[64 * 128];
    const int l = threadIdx.x & 31;
    const int w = threadIdx.x >> 5;
    const int rowBase = blockIdx.x * 64 + w * 8;

    float acc[8][4];
#pragma unroll
    for (int r = 0; r < 8; ++r)
#pragma unroll
        for (int c = 0; c < 4; ++c) acc[r][c] = 0.f;

#pragma unroll
    for (int half = 0; half < 2; ++half) {
        __syncthreads();
        // stage W[half*64 .. half*64+64) x [0,128) : 8192 floats, float4 loads
        {
            const float4* src = (const float4*)(W + half * 64 * 128);
            float4* dst = (float4*)Ws;
            for (int i = threadIdx.x; i < 64 * 128 / 4; i += 256) dst[i] = src[i];
        }
        __syncthreads();

#pragma unroll
        for (int kc = 0; kc < 16; ++kc) {
            float a[8][4];
#pragma unroll
            for (int r = 0; r < 8; ++r) {
                int row = rowBase + r;
                if (row >= Nn) row = Nn - 1;               // clamp (store guarded)
                float4 t = *(const float4*)(A + (size_t)row * 128 + half * 64 + kc * 4);
                a[r][0] = t.x; a[r][1] = t.y; a[r][2] = t.z; a[r][3] = t.w;
            }
#pragma unroll
            for (int j = 0; j < 4; ++j) {
                const int k = kc * 4 + j;
                const float w0 = Ws[k * 128 + l];
                const float w1 = Ws[k * 128 + l + 32];
                const float w2 = Ws[k * 128 + l + 64];
                const float w3 = Ws[k * 128 + l + 96];
#pragma unroll
                for (int r = 0; r < 8; ++r) {
                    acc[r][0] += a[r][j] * w0;
                    acc[r][1] += a[r][j] * w1;
                    acc[r][2] += a[r][j] * w2;
                    acc[r][3] += a[r][j] * w3;
                }
            }
        }
    }

    // epilogue: store h and fused alpha projections.
    // feature index f = l + 32*c -> head = c, within-head channel = l
    float* hbase = (float*)g_h;
#pragma unroll
    for (int r = 0; r < 8; ++r) {
        const int row = rowBase + r;
        if (row >= Nn) break;                              // uniform across warp
        float* o = hbase + (size_t)row * 128;
        o[l] = acc[r][0]; o[l + 32] = acc[r][1]; o[l + 64] = acc[r][2]; o[l + 96] = acc[r][3];

        float ps[4], pd[4];
#pragma unroll
        for (int c = 0; c < 4; ++c) {
            const float cs = a_s[c * 32 + l];
            const float cd = a_d[c * 32 + l];
            ps[c] = acc[r][c] * cs;
            pd[c] = acc[r][c] * cd;
        }
#pragma unroll
        for (int off = 16; off; off >>= 1) {
#pragma unroll
            for (int c = 0; c < 4; ++c) {
                ps[c] += __shfl_xor_sync(0xffffffffu, ps[c], off);
                pd[c] += __shfl_xor_sync(0xffffffffu, pd[c], off);
            }
        }
        if (l == 0) {
            g_as[row] = make_float4(ps[0], ps[1], ps[2], ps[3]);
            g_ad[row] = make_float4(pd[0], pd[1], pd[2], pd[3]);
        }
    }
}

// init: m = -inf, den = 0, out accumulator = 0
__global__ void k_init(float* __restrict__ out, int Nn) {
    const int i = blockIdx.x * 256 + threadIdx.x;
    if (i < Nn * 4) {
        ((float*)g_m)[i]   = __int_as_float(0xff800000);   // -inf
        ((float*)g_den)[i] = 0.f;
    }
    if (i < Nn * 128) out[i] = 0.f;
}

// pass 1: segment max of leaky_relu(as[src]+ad[dst]) per (dst, head)
__global__ void k_edge_max(const void* __restrict__ ei, int E, int ET) {
    const int e = blockIdx.x * 256 + threadIdx.x;
    if (e >= ET) return;
    const int2 sd = get_edge(ei, e, E);
    const float4 s = g_as[sd.x];
    const float4 d = g_ad[sd.y];
    float* m = (float*)&g_m[sd.y];
    atomicMaxF(m + 0, lrelu(s.x + d.x));
    atomicMaxF(m + 1, lrelu(s.y + d.y));
    atomicMaxF(m + 2, lrelu(s.z + d.z));
    atomicMaxF(m + 3, lrelu(s.w + d.w));
}

// pass 2: e' = exp(e - m[dst]); store per edge; den[dst] += e'  (vector RED)
__global__ void k_edge_exp(const void* __restrict__ ei, int E, int ET) {
    const int e = blockIdx.x * 256 + threadIdx.x;
    if (e >= ET) return;
    const int2 sd = get_edge(ei, e, E);
    const float4 s = g_as[sd.x];
    const float4 d = g_ad[sd.y];
    const float4 mm = g_m[sd.y];
    float4 v;
    v.x = __expf(lrelu(s.x + d.x) - mm.x);
    v.y = __expf(lrelu(s.y + d.y) - mm.y);
    v.z = __expf(lrelu(s.z + d.z) - mm.z);
    v.w = __expf(lrelu(s.w + d.w) - mm.w);
    g_eexp[e] = v;
    red_add_v4(&g_den[sd.y], v);
}

// pass 3: out[dst] += h[src] * alpha.  One warp per edge:
// lane handles float4 at feature offset lane*4 -> head = lane>>3.
__global__ void k_edge_agg(const void* __restrict__ ei, float4* __restrict__ out,
                           int E, int ET) {
    const long long t = (long long)blockIdx.x * 256 + threadIdx.x;
    const int e = (int)(t >> 5);
    const int lane = (int)(t & 31);
    if (e >= ET) return;
    const int2 sd = get_edge(ei, e, E);
    const int head = lane >> 3;
    const float num = ((const float*)g_eexp)[(size_t)e * 4 + head];
    const float den = ((const float*)g_den)[(size_t)sd.y * 4 + head];
    const float alpha = __fdividef(num, den);
    const float4 hv = g_h[(size_t)sd.x * 32 + lane];
    red_add_v4(out + (size_t)sd.y * 32 + lane,
               make_float4(hv.x * alpha, hv.y * alpha, hv.z * alpha, hv.w * alpha));
}

// out = relu(out + b)
__global__ void k_bias_relu(float* __restrict__ out, const float* __restrict__ b, int Nn) {
    const int i = blockIdx.x * 256 + threadIdx.x;
    if (i >= Nn * 128) return;
    out[i] = fmaxf(out[i] + b[i & 127], 0.f);
}

// ---------------- launch -----------------------------------------------------
extern "C" void kernel_launch(void* const* d_in, const int* in_sizes, int n_in,
                              void* d_out, int out_size) {
    const float* x   = (const float*)d_in[0];
    const void*  ei  = d_in[1];
    const float* W1  = (const float*)d_in[2];
    const float* as1 = (const float*)d_in[3];
    const float* ad1 = (const float*)d_in[4];
    const float* b1  = (const float*)d_in[5];
    const float* W2  = (const float*)d_in[6];
    const float* as2 = (const float*)d_in[7];
    const float* ad2 = (const float*)d_in[8];
    const float* b2  = (const float*)d_in[9];

    const int N  = in_sizes[0] / 128;
    const int E  = in_sizes[1] / 2;
    const int ET = E + N;

    void* pout = nullptr;
    cudaGetSymbolAddress(&pout, g_out);

    const int ebl  = (ET + 255) / 256;
    const int nbl  = (N * 128 + 255) / 256;
    const long long aggT = (long long)ET * 32;
    const int abl  = (int)((aggT + 255) / 256);
    const int gbl  = (N + 63) / 64;

    k_detect<<<1, 32>>>((const int*)ei);

    // ---- layer 1 ----
    k_gemm<<<gbl, 256>>>(x, W1, as1, ad1, N);
    k_init<<<nbl, 256>>>((float*)pout, N);
    k_edge_max<<<ebl, 256>>>(ei, E, ET);
    k_edge_exp<<<ebl, 256>>>(ei, E, ET);
    k_edge_agg<<<abl, 256>>>(ei, (float4*)pout, E, ET);
    k_bias_relu<<<nbl, 256>>>((float*)pout, b1, N);

    // ---- layer 2 ----
    k_gemm<<<gbl, 256>>>((const float*)pout, W2, as2, ad2, N);
    k_init<<<nbl, 256>>>((float*)d_out, N);
    k_edge_max<<<ebl, 256>>>(ei, E, ET);
    k_edge_exp<<<ebl, 256>>>(ei, E, ET);
    k_edge_agg<<<abl, 256>>>(ei, (float4*)d_out, E, ET);
    k_bias_relu<<<nbl, 256>>>((float*)d_out, b2, N);
}

// round 2
// speedup vs baseline: 1.7557x; 1.7557x over previous
#include <cuda_runtime.h>
#include <cstdint>

// Problem shape (fixed by the dataset): N=100000 nodes, E=1600000 edges,
// D = H*C = 128, H=4 heads, C=32.
#define N_MAX  100000
#define E_MAX  1600000
#define NEG_SLOPE 0.2f

// ---------------- scratch (device globals; no allocation APIs allowed) ------
__device__ int    g_is64;                 // edge_index dtype flag (1 = int64)
__device__ float4 g_h[N_MAX * 32];        // transformed features h = x@W, [N,128]
__device__ float4 g_as[N_MAX];            // alpha_src per node [N,4]
__device__ float4 g_ad[N_MAX];            // alpha_dst per node [N,4]
__device__ float4 g_out[N_MAX * 32];      // layer-1 output / layer-2 input
__device__ int    g_deg[N_MAX];           // in-degree (real edges only)
__device__ int    g_rowp[N_MAX + 1];      // CSR row pointers
__device__ int    g_cursor[N_MAX];        // scatter cursors
__device__ int    g_csrc[E_MAX];          // CSR src indices (sorted by dst)

// ---------------- helpers ----------------------------------------------------
__device__ __forceinline__ float lrelu(float x) { return x > 0.f ? x : NEG_SLOPE * x; }

__device__ __forceinline__ int2 get_edge(const void* ei, int e, int E) {
    if (g_is64) {
        const long long* p = (const long long*)ei;
        return make_int2((int)p[e], (int)p[E + e]);
    } else {
        const int* p = (const int*)ei;
        return make_int2(p[e], p[E + e]);
    }
}

// ---------------- kernels ----------------------------------------------------

// detect int64 vs int32 edge_index: int64 little-endian => odd int32 words are 0
__global__ void k_detect(const int* __restrict__ p) {
    if (threadIdx.x == 0 && blockIdx.x == 0) {
        int is64 = 1;
        for (int i = 1; i < 128; i += 2)
            if (p[i] != 0) { is64 = 0; break; }
        g_is64 = is64;
    }
}

// zero degree counters
__global__ void k_zero_deg(int Nn) {
    const int i = blockIdx.x * 256 + threadIdx.x;
    if (i < Nn) g_deg[i] = 0;
}

// histogram of dst
__global__ void k_hist(const void* __restrict__ ei, int E) {
    const int e = blockIdx.x * 256 + threadIdx.x;
    if (e >= E) return;
    const int2 sd = get_edge(ei, e, E);
    atomicAdd(&g_deg[sd.y], 1);
}

// single-block prefix scan over N degrees -> row_ptr, cursor
__global__ __launch_bounds__(1024)
void k_scan(int Nn) {
    __shared__ int sm[1024];
    __shared__ int carry;
    const int t = threadIdx.x;
    if (t == 0) { carry = 0; g_rowp[0] = 0; }
    __syncthreads();
    for (int base = 0; base < Nn; base += 1024) {
        const int i = base + t;
        int v = (i < Nn) ? g_deg[i] : 0;
        sm[t] = v;
        __syncthreads();
        // Hillis-Steele inclusive scan
        for (int off = 1; off < 1024; off <<= 1) {
            int add = (t >= off) ? sm[t - off] : 0;
            __syncthreads();
            sm[t] += add;
            __syncthreads();
        }
        if (i < Nn) {
            const int incl = sm[t] + carry;
            g_rowp[i + 1] = incl;
            g_cursor[i]   = incl - v;   // exclusive
        }
        __syncthreads();
        if (t == 0) carry += sm[1023];
        __syncthreads();
    }
}

// scatter src indices into CSR order
__global__ void k_scatter(const void* __restrict__ ei, int E) {
    const int e = blockIdx.x * 256 + threadIdx.x;
    if (e >= E) return;
    const int2 sd = get_edge(ei, e, E);
    const int pos = atomicAdd(&g_cursor[sd.y], 1);
    g_csrc[pos] = sd.x;
}

// h = A @ W  (A: [N,128], W: [128,128]) with fused alpha_src/alpha_dst epilogue.
__global__ __launch_bounds__(256)
void k_gemm(const float* __restrict__ A, const float* __restrict__ W,
            const float* __restrict__ a_s, const float* __restrict__ a_d, int Nn) {
    __shared__ float Ws[64 * 128];
    const int l = threadIdx.x & 31;
    const int w = threadIdx.x >> 5;
    const int rowBase = blockIdx.x * 64 + w * 8;

    float acc[8][4];
#pragma unroll
    for (int r = 0; r < 8; ++r)
#pragma unroll
        for (int c = 0; c < 4; ++c) acc[r][c] = 0.f;

#pragma unroll
    for (int half = 0; half < 2; ++half) {
        __syncthreads();
        {
            const float4* src = (const float4*)(W + half * 64 * 128);
            float4* dst = (float4*)Ws;
            for (int i = threadIdx.x; i < 64 * 128 / 4; i += 256) dst[i] = src[i];
        }
        __syncthreads();

#pragma unroll
        for (int kc = 0; kc < 16; ++kc) {
            float a[8][4];
#pragma unroll
            for (int r = 0; r < 8; ++r) {
                int row = rowBase + r;
                if (row >= Nn) row = Nn - 1;               // clamp (store guarded)
                float4 t = *(const float4*)(A + (size_t)row * 128 + half * 64 + kc * 4);
                a[r][0] = t.x; a[r][1] = t.y; a[r][2] = t.z; a[r][3] = t.w;
            }
#pragma unroll
            for (int j = 0; j < 4; ++j) {
                const int k = kc * 4 + j;
                const float w0 = Ws[k * 128 + l];
                const float w1 = Ws[k * 128 + l + 32];
                const float w2 = Ws[k * 128 + l + 64];
                const float w3 = Ws[k * 128 + l + 96];
#pragma unroll
                for (int r = 0; r < 8; ++r) {
                    acc[r][0] += a[r][j] * w0;
                    acc[r][1] += a[r][j] * w1;
                    acc[r][2] += a[r][j] * w2;
                    acc[r][3] += a[r][j] * w3;
                }
            }
        }
    }

    float* hbase = (float*)g_h;
#pragma unroll
    for (int r = 0; r < 8; ++r) {
        const int row = rowBase + r;
        if (row >= Nn) break;                              // uniform across warp
        float* o = hbase + (size_t)row * 128;
        o[l] = acc[r][0]; o[l + 32] = acc[r][1]; o[l + 64] = acc[r][2]; o[l + 96] = acc[r][3];

        float ps[4], pd[4];
#pragma unroll
        for (int c = 0; c < 4; ++c) {
            const float cs = a_s[c * 32 + l];
            const float cd = a_d[c * 32 + l];
            ps[c] = acc[r][c] * cs;
            pd[c] = acc[r][c] * cd;
        }
#pragma unroll
        for (int off = 16; off; off >>= 1) {
#pragma unroll
            for (int c = 0; c < 4; ++c) {
                ps[c] += __shfl_xor_sync(0xffffffffu, ps[c], off);
                pd[c] += __shfl_xor_sync(0xffffffffu, pd[c], off);
            }
        }
        if (l == 0) {
            g_as[row] = make_float4(ps[0], ps[1], ps[2], ps[3]);
            g_ad[row] = make_float4(pd[0], pd[1], pd[2], pd[3]);
        }
    }
}

// Fused GAT aggregation: one warp per destination node.
// Computes softmax weights (no max shift; logits are O(1)) over the self-loop
// + incoming edges, accumulates sum(w * h[src]) and sum(w) in registers,
// writes relu(acc/den + bias) directly.
__global__ __launch_bounds__(256)
void k_gat_agg(const float4* __restrict__ h, float4* __restrict__ out,
               const float* __restrict__ bias, int Nn) {
    __shared__ float wsm[8][32][4];
    __shared__ int   ssm[8][32];

    const int warp = (blockIdx.x * 256 + threadIdx.x) >> 5;
    const int lane = threadIdx.x & 31;
    const int w    = threadIdx.x >> 5;
    if (warp >= Nn) return;
    const int v = warp;
    const int head = lane >> 3;

    const float4 adv = g_ad[v];

    // self-loop contribution
    float4 acc;
    float  den;
    {
        const float4 asv = g_as[v];
        float4 we;
        we.x = __expf(lrelu(asv.x + adv.x));
        we.y = __expf(lrelu(asv.y + adv.y));
        we.z = __expf(lrelu(asv.z + adv.z));
        we.w = __expf(lrelu(asv.w + adv.w));
        const float wh = (head == 0) ? we.x : (head == 1) ? we.y : (head == 2) ? we.z : we.w;
        const float4 hv = h[(size_t)v * 32 + lane];
        acc = make_float4(hv.x * wh, hv.y * wh, hv.z * wh, hv.w * wh);
        den = wh;
    }

    const int beg = g_rowp[v];
    const int end = g_rowp[v + 1];
    for (int base = beg; base < end; base += 32) {
        int n = end - base; if (n > 32) n = 32;
        int sidx = 0;
        float4 we = make_float4(0.f, 0.f, 0.f, 0.f);
        if (lane < n) {
            sidx = g_csrc[base + lane];
            const float4 s = g_as[sidx];
            we.x = __expf(lrelu(s.x + adv.x));
            we.y = __expf(lrelu(s.y + adv.y));
            we.z = __expf(lrelu(s.z + adv.z));
            we.w = __expf(lrelu(s.w + adv.w));
        }
        ssm[w][lane] = sidx;
        *(float4*)&wsm[w][lane][0] = we;
        __syncwarp();
        for (int j = 0; j < n; ++j) {
            const int   sj = ssm[w][j];
            const float wj = wsm[w][j][head];
            const float4 hv = h[(size_t)sj * 32 + lane];
            acc.x += wj * hv.x;
            acc.y += wj * hv.y;
            acc.z += wj * hv.z;
            acc.w += wj * hv.w;
            den   += wj;
        }
        __syncwarp();
    }

    const float inv = __fdividef(1.f, den);
    const float4 b4 = ((const float4*)bias)[lane];
    float4 o;
    o.x = fmaxf(acc.x * inv + b4.x, 0.f);
    o.y = fmaxf(acc.y * inv + b4.y, 0.f);
    o.z = fmaxf(acc.z * inv + b4.z, 0.f);
    o.w = fmaxf(acc.w * inv + b4.w, 0.f);
    out[(size_t)v * 32 + lane] = o;
}

// ---------------- launch -----------------------------------------------------
extern "C" void kernel_launch(void* const* d_in, const int* in_sizes, int n_in,
                              void* d_out, int out_size) {
    const float* x   = (const float*)d_in[0];
    const void*  ei  = d_in[1];
    const float* W1  = (const float*)d_in[2];
    const float* as1 = (const float*)d_in[3];
    const float* ad1 = (const float*)d_in[4];
    const float* b1  = (const float*)d_in[5];
    const float* W2  = (const float*)d_in[6];
    const float* as2 = (const float*)d_in[7];
    const float* ad2 = (const float*)d_in[8];
    const float* b2  = (const float*)d_in[9];

    const int N  = in_sizes[0] / 128;
    const int E  = in_sizes[1] / 2;

    void* ph = nullptr;  cudaGetSymbolAddress(&ph,  g_h);
    void* po = nullptr;  cudaGetSymbolAddress(&po,  g_out);

    const int ebl = (E + 255) / 256;
    const int nbl = (N + 255) / 256;
    const int abl = (N * 32 + 255) / 256;
    const int gbl = (N + 63) / 64;

    k_detect<<<1, 32>>>((const int*)ei);

    // ---- CSR build (shared by both layers) ----
    k_zero_deg<<<nbl, 256>>>(N);
    k_hist<<<ebl, 256>>>(ei, E);
    k_scan<<<1, 1024>>>(N);
    k_scatter<<<ebl, 256>>>(ei, E);

    // ---- layer 1 ----
    k_gemm<<<gbl, 256>>>(x, W1, as1, ad1, N);
    k_gat_agg<<<abl, 256>>>((const float4*)ph, (float4*)po, b1, N);

    // ---- layer 2 ----
    k_gemm<<<gbl, 256>>>((const float*)po, W2, as2, ad2, N);
    k_gat_agg<<<abl, 256>>>((const float4*)ph, (float4*)d_out, b2, N);
}

// round 3
// speedup vs baseline: 2.2888x; 1.3036x over previous
#include <cuda_runtime.h>
#include <cstdint>

// Problem shape (fixed by the dataset): N=100000 nodes, E=1600000 edges,
// D = H*C = 128, H=4 heads, C=32.
#define N_MAX  100000
#define E_MAX  1600000
#define NEG_SLOPE 0.2f

#define SCAN_CHUNK 4096          // elems per scan block (1024 thr x 4)
#define SCAN_PARTS ((N_MAX + SCAN_CHUNK - 1) / SCAN_CHUNK + 1)

// ---------------- scratch (device globals; no allocation APIs allowed) ------
__device__ int    g_is64;                 // edge_index dtype flag (1 = int64)
__device__ float4 g_h[N_MAX * 32];        // transformed features h = x@W, [N,128]
__device__ float4 g_as[N_MAX];            // alpha_src per node [N,4]
__device__ float4 g_ad[N_MAX];            // alpha_dst per node [N,4]
__device__ float4 g_out[N_MAX * 32];      // layer-1 output / layer-2 input
__device__ int    g_deg[N_MAX];           // in-degree (real edges only)
__device__ int    g_rowp[N_MAX + 1];      // CSR row pointers
__device__ int    g_cursor[N_MAX];        // scatter cursors
__device__ int    g_csrc[E_MAX];          // CSR src indices (sorted by dst)
__device__ int    g_part[64];             // scan block partials / exclusive offsets

// ---------------- helpers ----------------------------------------------------
__device__ __forceinline__ float lrelu(float x) { return x > 0.f ? x : NEG_SLOPE * x; }

__device__ __forceinline__ int2 get_edge(const void* ei, int e, int E) {
    if (g_is64) {
        const long long* p = (const long long*)ei;
        return make_int2((int)p[e], (int)p[E + e]);
    } else {
        const int* p = (const int*)ei;
        return make_int2(p[e], p[E + e]);
    }
}

// ---------------- kernels ----------------------------------------------------

// detect int64 vs int32 edge_index: int64 little-endian => odd int32 words are 0
__global__ void k_detect(const int* __restrict__ p) {
    if (threadIdx.x == 0 && blockIdx.x == 0) {
        int is64 = 1;
        for (int i = 1; i < 128; i += 2)
            if (p[i] != 0) { is64 = 0; break; }
        g_is64 = is64;
    }
}

// zero degree counters
__global__ void k_zero_deg(int Nn) {
    const int i = blockIdx.x * 256 + threadIdx.x;
    if (i < Nn) g_deg[i] = 0;
}

// histogram of dst
__global__ void k_hist(const void* __restrict__ ei, int E) {
    const int e = blockIdx.x * 256 + threadIdx.x;
    if (e >= E) return;
    const int2 sd = get_edge(ei, e, E);
    atomicAdd(&g_deg[sd.y], 1);
}

// ---- multi-block exclusive scan over degrees -> rowp, cursor ----
// phase 1: per-block sums
__global__ __launch_bounds__(1024)
void k_blockred(int Nn) {
    const int t = threadIdx.x;
    const int base = blockIdx.x * SCAN_CHUNK + t * 4;
    int s = 0;
#pragma unroll
    for (int i = 0; i < 4; ++i) {
        const int idx = base + i;
        if (idx < Nn) s += g_deg[idx];
    }
#pragma unroll
    for (int off = 16; off; off >>= 1) s += __shfl_xor_sync(0xffffffffu, s, off);
    __shared__ int wsum[32];
    if ((t & 31) == 0) wsum[t >> 5] = s;
    __syncthreads();
    if (t < 32) {
        int v = wsum[t];
#pragma unroll
        for (int off = 16; off; off >>= 1) v += __shfl_xor_sync(0xffffffffu, v, off);
        if (t == 0) g_part[blockIdx.x] = v;
    }
}

// phase 2: exclusive scan of the (<=63) partials; also rowp[0]=0
__global__ void k_scanpart(int nparts) {
    if (threadIdx.x == 0) {
        int run = 0;
        for (int i = 0; i < nparts; ++i) {
            const int v = g_part[i];
            g_part[i] = run;
            run += v;
        }
        g_rowp[0] = 0;
    }
}

// phase 3: per-block scan + global offset -> rowp (inclusive at i+1), cursor (exclusive)
__global__ __launch_bounds__(1024)
void k_blockscan(int Nn) {
    __shared__ int wsum[32];
    const int t = threadIdx.x;
    const int lane = t & 31;
    const int wid  = t >> 5;
    const int base = blockIdx.x * SCAN_CHUNK + t * 4;

    int vals[4];
    int local = 0;
#pragma unroll
    for (int i = 0; i < 4; ++i) {
        const int idx = base + i;
        vals[i] = (idx < Nn) ? g_deg[idx] : 0;
        local += vals[i];
    }
    // warp inclusive scan of per-thread sums
    int x = local;
#pragma unroll
    for (int off = 1; off < 32; off <<= 1) {
        const int n = __shfl_up_sync(0xffffffffu, x, off);
        if (lane >= off) x += n;
    }
    if (lane == 31) wsum[wid] = x;
    __syncthreads();
    if (wid == 0) {
        int v = (lane < 32) ? wsum[lane] : 0;
#pragma unroll
        for (int off = 1; off < 32; off <<= 1) {
            const int n = __shfl_up_sync(0xffffffffu, v, off);
            if (lane >= off) v += n;
        }
        wsum[lane] = v;
    }
    __syncthreads();
    const int warpoff = (wid > 0) ? wsum[wid - 1] : 0;
    int run = g_part[blockIdx.x] + warpoff + (x - local);   // exclusive prefix of this thread
#pragma unroll
    for (int i = 0; i < 4; ++i) {
        const int idx = base + i;
        if (idx < Nn) {
            g_cursor[idx]   = run;
            g_rowp[idx + 1] = run + vals[i];
        }
        run += vals[i];
    }
}

// scatter src indices into CSR order
__global__ void k_scatter(const void* __restrict__ ei, int E) {
    const int e = blockIdx.x * 256 + threadIdx.x;
    if (e >= E) return;
    const int2 sd = get_edge(ei, e, E);
    const int pos = atomicAdd(&g_cursor[sd.y], 1);
    g_csrc[pos] = sd.x;
}

// h = A @ W  (A: [N,128], W: [128,128]) with fused alpha_src/alpha_dst epilogue.
__global__ __launch_bounds__(256)
void k_gemm(const float* __restrict__ A, const float* __restrict__ W,
            const float* __restrict__ a_s, const float* __restrict__ a_d, int Nn) {
    __shared__ float Ws[64 * 128];
    const int l = threadIdx.x & 31;
    const int w = threadIdx.x >> 5;
    const int rowBase = blockIdx.x * 64 + w * 8;

    float acc[8][4];
#pragma unroll
    for (int r = 0; r < 8; ++r)
#pragma unroll
        for (int c = 0; c < 4; ++c) acc[r][c] = 0.f;

#pragma unroll
    for (int half = 0; half < 2; ++half) {
        __syncthreads();
        {
            const float4* src = (const float4*)(W + half * 64 * 128);
            float4* dst = (float4*)Ws;
            for (int i = threadIdx.x; i < 64 * 128 / 4; i += 256) dst[i] = src[i];
        }
        __syncthreads();

#pragma unroll
        for (int kc = 0; kc < 16; ++kc) {
            float a[8][4];
#pragma unroll
            for (int r = 0; r < 8; ++r) {
                int row = rowBase + r;
                if (row >= Nn) row = Nn - 1;               // clamp (store guarded)
                float4 t = *(const float4*)(A + (size_t)row * 128 + half * 64 + kc * 4);
                a[r][0] = t.x; a[r][1] = t.y; a[r][2] = t.z; a[r][3] = t.w;
            }
#pragma unroll
            for (int j = 0; j < 4; ++j) {
                const int k = kc * 4 + j;
                const float w0 = Ws[k * 128 + l];
                const float w1 = Ws[k * 128 + l + 32];
                const float w2 = Ws[k * 128 + l + 64];
                const float w3 = Ws[k * 128 + l + 96];
#pragma unroll
                for (int r = 0; r < 8; ++r) {
                    acc[r][0] += a[r][j] * w0;
                    acc[r][1] += a[r][j] * w1;
                    acc[r][2] += a[r][j] * w2;
                    acc[r][3] += a[r][j] * w3;
                }
            }
        }
    }

    float* hbase = (float*)g_h;
#pragma unroll
    for (int r = 0; r < 8; ++r) {
        const int row = rowBase + r;
        if (row >= Nn) break;                              // uniform across warp
        float* o = hbase + (size_t)row * 128;
        o[l] = acc[r][0]; o[l + 32] = acc[r][1]; o[l + 64] = acc[r][2]; o[l + 96] = acc[r][3];

        float ps[4], pd[4];
#pragma unroll
        for (int c = 0; c < 4; ++c) {
            const float cs = a_s[c * 32 + l];
            const float cd = a_d[c * 32 + l];
            ps[c] = acc[r][c] * cs;
            pd[c] = acc[r][c] * cd;
        }
#pragma unroll
        for (int off = 16; off; off >>= 1) {
#pragma unroll
            for (int c = 0; c < 4; ++c) {
                ps[c] += __shfl_xor_sync(0xffffffffu, ps[c], off);
                pd[c] += __shfl_xor_sync(0xffffffffu, pd[c], off);
            }
        }
        if (l == 0) {
            g_as[row] = make_float4(ps[0], ps[1], ps[2], ps[3]);
            g_ad[row] = make_float4(pd[0], pd[1], pd[2], pd[3]);
        }
    }
}

// Fused GAT aggregation: one warp per destination node.
__global__ __launch_bounds__(256)
void k_gat_agg(const float4* __restrict__ h, float4* __restrict__ out,
               const float* __restrict__ bias, int Nn) {
    __shared__ float wsm[8][32][4];
    __shared__ int   ssm[8][32];

    const int warp = (blockIdx.x * 256 + threadIdx.x) >> 5;
    const int lane = threadIdx.x & 31;
    const int w    = threadIdx.x >> 5;
    if (warp >= Nn) return;
    const int v = warp;
    const int head = lane >> 3;

    const float4 adv = g_ad[v];

    // self-loop contribution
    float4 acc;
    float  den;
    {
        const float4 asv = g_as[v];
        float4 we;
        we.x = __expf(lrelu(asv.x + adv.x));
        we.y = __expf(lrelu(asv.y + adv.y));
        we.z = __expf(lrelu(asv.z + adv.z));
        we.w = __expf(lrelu(asv.w + adv.w));
        const float wh = (head == 0) ? we.x : (head == 1) ? we.y : (head == 2) ? we.z : we.w;
        const float4 hv = h[(size_t)v * 32 + lane];
        acc = make_float4(hv.x * wh, hv.y * wh, hv.z * wh, hv.w * wh);
        den = wh;
    }

    const int beg = g_rowp[v];
    const int end = g_rowp[v + 1];
    for (int base = beg; base < end; base += 32) {
        int n = end - base; if (n > 32) n = 32;
        int sidx = 0;
        float4 we = make_float4(0.f, 0.f, 0.f, 0.f);
        if (lane < n) {
            sidx = g_csrc[base + lane];
            const float4 s = g_as[sidx];
            we.x = __expf(lrelu(s.x + adv.x));
            we.y = __expf(lrelu(s.y + adv.y));
            we.z = __expf(lrelu(s.z + adv.z));
            we.w = __expf(lrelu(s.w + adv.w));
        }
        ssm[w][lane] = sidx;
        *(float4*)&wsm[w][lane][0] = we;
        __syncwarp();
        for (int j = 0; j < n; ++j) {
            const int   sj = ssm[w][j];
            const float wj = wsm[w][j][head];
            const float4 hv = h[(size_t)sj * 32 + lane];
            acc.x += wj * hv.x;
            acc.y += wj * hv.y;
            acc.z += wj * hv.z;
            acc.w += wj * hv.w;
            den   += wj;
        }
        __syncwarp();
    }

    const float inv = __fdividef(1.f, den);
    const float4 b4 = ((const float4*)bias)[lane];
    float4 o;
    o.x = fmaxf(acc.x * inv + b4.x, 0.f);
    o.y = fmaxf(acc.y * inv + b4.y, 0.f);
    o.z = fmaxf(acc.z * inv + b4.z, 0.f);
    o.w = fmaxf(acc.w * inv + b4.w, 0.f);
    out[(size_t)v * 32 + lane] = o;
}

// ---------------- launch -----------------------------------------------------
extern "C" void kernel_launch(void* const* d_in, const int* in_sizes, int n_in,
                              void* d_out, int out_size) {
    const float* x   = (const float*)d_in[0];
    const void*  ei  = d_in[1];
    const float* W1  = (const float*)d_in[2];
    const float* as1 = (const float*)d_in[3];
    const float* ad1 = (const float*)d_in[4];
    const float* b1  = (const float*)d_in[5];
    const float* W2  = (const float*)d_in[6];
    const float* as2 = (const float*)d_in[7];
    const float* ad2 = (const float*)d_in[8];
    const float* b2  = (const float*)d_in[9];

    const int N  = in_sizes[0] / 128;
    const int E  = in_sizes[1] / 2;

    void* ph = nullptr;  cudaGetSymbolAddress(&ph,  g_h);
    void* po = nullptr;  cudaGetSymbolAddress(&po,  g_out);

    const int ebl = (E + 255) / 256;
    const int nbl = (N + 255) / 256;
    const int abl = (N * 32 + 255) / 256;
    const int gbl = (N + 63) / 64;
    const int sbl = (N + SCAN_CHUNK - 1) / SCAN_CHUNK;

    k_detect<<<1, 32>>>((const int*)ei);

    // ---- CSR build (shared by both layers) ----
    k_zero_deg<<<nbl, 256>>>(N);
    k_hist<<<ebl, 256>>>(ei, E);
    k_blockred<<<sbl, 1024>>>(N);
    k_scanpart<<<1, 32>>>(sbl);
    k_blockscan<<<sbl, 1024>>>(N);
    k_scatter<<<ebl, 256>>>(ei, E);

    // ---- layer 1 ----
    k_gemm<<<gbl, 256>>>(x, W1, as1, ad1, N);
    k_gat_agg<<<abl, 256>>>((const float4*)ph, (float4*)po, b1, N);

    // ---- layer 2 ----
    k_gemm<<<gbl, 256>>>((const float*)po, W2, as2, ad2, N);
    k_gat_agg<<<abl, 256>>>((const float4*)ph, (float4*)d_out, b2, N);
}

// round 5
// speedup vs baseline: 2.5301x; 1.1055x over previous
#include <cuda_runtime.h>
#include <cuda_bf16.h>
#include <cstdint>

// Problem shape: N=100000 nodes, E=1600000 edges, D = H*C = 128, H=4, C=32.
#define N_MAX  100000
#define E_MAX  1600000
#define NEG_SLOPE 0.2f
#define SCAN_CHUNK 4096

// ---------------- scratch (device globals) ----------------------------------
__device__ int    g_is64;
__device__ float4 g_h[N_MAX * 32];        // h = x@W, [N,128]
__device__ float4 g_as[N_MAX];            // alpha_src per node [N,4]
__device__ float4 g_ad[N_MAX];            // alpha_dst per node [N,4]
__device__ float4 g_out[N_MAX * 32];      // layer-1 output
__device__ int    g_deg[N_MAX];
__device__ int    g_rowp[N_MAX + 1];
__device__ int    g_cursor[N_MAX];
__device__ int    g_csrc[E_MAX];
__device__ int    g_part[64];
// W in bf16 hi/lo, pre-packed into mma.m16n8k16 B-fragment order:
// halves index = ((kk*16 + j)*32 + lane)*4 + reg*2 + half
__device__ unsigned short g_whi[2][16384];
__device__ unsigned short g_wlo[2][16384];

// ---------------- helpers ----------------------------------------------------
__device__ __forceinline__ float lrelu(float x) { return x > 0.f ? x : NEG_SLOPE * x; }

__device__ __forceinline__ int2 get_edge(const void* ei, int e, int E) {
    if (g_is64) {
        const long long* p = (const long long*)ei;
        return make_int2((int)p[e], (int)p[E + e]);
    } else {
        const int* p = (const int*)ei;
        return make_int2(p[e], p[E + e]);
    }
}

__device__ __forceinline__ void mma_bf16(float* c, uint32_t a0, uint32_t a1,
                                         uint32_t a2, uint32_t a3,
                                         uint32_t b0, uint32_t b1) {
    asm volatile(
        "mma.sync.aligned.m16n8k16.row.col.f32.bf16.bf16.f32 "
        "{%0,%1,%2,%3}, {%4,%5,%6,%7}, {%8,%9}, {%0,%1,%2,%3};"
        : "+f"(c[0]), "+f"(c[1]), "+f"(c[2]), "+f"(c[3])
        : "r"(a0), "r"(a1), "r"(a2), "r"(a3), "r"(b0), "r"(b1));
}

// ---------------- misc kernels ----------------------------------------------
__global__ void k_detect(const int* __restrict__ p) {
    if (threadIdx.x == 0 && blockIdx.x == 0) {
        int is64 = 1;
        for (int i = 1; i < 128; i += 2)
            if (p[i] != 0) { is64 = 0; break; }
        g_is64 = is64;
    }
}

__global__ void k_zero_deg(int Nn) {
    const int i = blockIdx.x * 256 + threadIdx.x;
    if (i < Nn) g_deg[i] = 0;
}

__global__ void k_hist(const void* __restrict__ ei, int E) {
    const int e = blockIdx.x * 256 + threadIdx.x;
    if (e >= E) return;
    const int2 sd = get_edge(ei, e, E);
    atomicAdd(&g_deg[sd.y], 1);
}

__global__ __launch_bounds__(1024)
void k_blockred(int Nn) {
    const int t = threadIdx.x;
    const int base = blockIdx.x * SCAN_CHUNK + t * 4;
    int s = 0;
#pragma unroll
    for (int i = 0; i < 4; ++i) {
        const int idx = base + i;
        if (idx < Nn) s += g_deg[idx];
    }
#pragma unroll
    for (int off = 16; off; off >>= 1) s += __shfl_xor_sync(0xffffffffu, s, off);
    __shared__ int wsum[32];
    if ((t & 31) == 0) wsum[t >> 5] = s;
    __syncthreads();
    if (t < 32) {
        int v = wsum[t];
#pragma unroll
        for (int off = 16; off; off >>= 1) v += __shfl_xor_sync(0xffffffffu, v, off);
        if (t == 0) g_part[blockIdx.x] = v;
    }
}

__global__ void k_scanpart(int nparts) {
    if (threadIdx.x == 0) {
        int run = 0;
        for (int i = 0; i < nparts; ++i) {
            const int v = g_part[i];
            g_part[i] = run;
            run += v;
        }
        g_rowp[0] = 0;
    }
}

__global__ __launch_bounds__(1024)
void k_blockscan(int Nn) {
    __shared__ int wsum[32];
    const int t = threadIdx.x;
    const int lane = t & 31;
    const int wid  = t >> 5;
    const int base = blockIdx.x * SCAN_CHUNK + t * 4;

    int vals[4];
    int local = 0;
#pragma unroll
    for (int i = 0; i < 4; ++i) {
        const int idx = base + i;
        vals[i] = (idx < Nn) ? g_deg[idx] : 0;
        local += vals[i];
    }
    int x = local;
#pragma unroll
    for (int off = 1; off < 32; off <<= 1) {
        const int n = __shfl_up_sync(0xffffffffu, x, off);
        if (lane >= off) x += n;
    }
    if (lane == 31) wsum[wid] = x;
    __syncthreads();
    if (wid == 0) {
        int v = wsum[lane];
#pragma unroll
        for (int off = 1; off < 32; off <<= 1) {
            const int n = __shfl_up_sync(0xffffffffu, v, off);
            if (lane >= off) v += n;
        }
        wsum[lane] = v;
    }
    __syncthreads();
    const int warpoff = (wid > 0) ? wsum[wid - 1] : 0;
    int run = g_part[blockIdx.x] + warpoff + (x - local);
#pragma unroll
    for (int i = 0; i < 4; ++i) {
        const int idx = base + i;
        if (idx < Nn) {
            g_cursor[idx]   = run;
            g_rowp[idx + 1] = run + vals[i];
        }
        run += vals[i];
    }
}

__global__ void k_scatter(const void* __restrict__ ei, int E) {
    const int e = blockIdx.x * 256 + threadIdx.x;
    if (e >= E) return;
    const int2 sd = get_edge(ei, e, E);
    const int pos = atomicAdd(&g_cursor[sd.y], 1);
    g_csrc[pos] = sd.x;
}

// ---- W prep: fp32 W[k,n] -> bf16 hi/lo in per-lane mma B-fragment order ----
__global__ void k_wprep(const float* __restrict__ W1, const float* __restrict__ W2) {
    const int idx = blockIdx.x * 256 + threadIdx.x;
    if (idx >= 32768) return;
    const int layer = idx >> 14;
    const int e = idx & 16383;
    const int k = e >> 7, n = e & 127;
    const float w = (layer ? W2 : W1)[k * 128 + n];
    __nv_bfloat16 hi = __float2bfloat16(w);
    __nv_bfloat16 lo = __float2bfloat16(w - __bfloat162float(hi));
    const int kk = k >> 4, kin = k & 15;
    const int reg = kin >> 3, t = (kin & 7) >> 1, half = kin & 1;
    const int j = n >> 3, g = n & 7;
    const int lane = g * 4 + t;
    const int off = ((kk * 16 + j) * 32 + lane) * 4 + reg * 2 + half;
    g_whi[layer][off] = *(unsigned short*)&hi;
    g_wlo[layer][off] = *(unsigned short*)&lo;
}

// ---- HMMA GEMM via mma.sync: 128-row tile per block (8 warps x 16 rows).
// D = Ahi*Bhi + Ahi*Blo + Alo*Bhi (split-bf16, fp32 register accumulate).
// Epilogue: store h + fused alpha projections.
#define SM_A_HI 0
#define SM_A_LO 34816
#define SM_W_HI 69632
#define SM_W_LO 102400
#define SMEM_SZ 135168
#define A_STRIDE 272   // bytes per A smem row (136 bf16) - conflict-free

__global__ __launch_bounds__(256, 1)
void k_gemm_mma(const float* __restrict__ A, int layer,
                const float* __restrict__ a_s, const float* __restrict__ a_d,
                float* __restrict__ hout, float4* __restrict__ asout,
                float4* __restrict__ adout, int Nn) {
    extern __shared__ __align__(16) char smem[];
    const int tid  = threadIdx.x;
    const int lane = tid & 31;
    const int wid  = tid >> 5;
    const int g    = lane >> 2;
    const int t    = lane & 3;
    const int rowBase = blockIdx.x * 128;

    // stage W fragments (hi/lo, 32KB each)
    {
        const uint4* shi = (const uint4*)g_whi[layer];
        const uint4* slo = (const uint4*)g_wlo[layer];
        uint4* dhi = (uint4*)(smem + SM_W_HI);
        uint4* dlo = (uint4*)(smem + SM_W_LO);
        for (int i = tid; i < 2048; i += 256) { dhi[i] = shi[i]; dlo[i] = slo[i]; }
    }
    // stage A: fp32 -> bf16 hi/lo, row stride 272B
    for (int idx = tid; idx < 4096; idx += 256) {
        const int r = idx >> 5;
        const int c4 = (idx & 31) * 4;
        int row = rowBase + r;
        if (row >= Nn) row = Nn - 1;
        const float4 v = *(const float4*)(A + (size_t)row * 128 + c4);
        __nv_bfloat16 hx = __float2bfloat16(v.x), hy = __float2bfloat16(v.y);
        __nv_bfloat16 hz = __float2bfloat16(v.z), hw = __float2bfloat16(v.w);
        __nv_bfloat16 lx = __float2bfloat16(v.x - __bfloat162float(hx));
        __nv_bfloat16 ly = __float2bfloat16(v.y - __bfloat162float(hy));
        __nv_bfloat16 lz = __float2bfloat16(v.z - __bfloat162float(hz));
        __nv_bfloat16 lw = __float2bfloat16(v.w - __bfloat162float(hw));
        uint2 ph, pl;
        ph.x = ((uint32_t)*(unsigned short*)&hy << 16) | *(unsigned short*)&hx;
        ph.y = ((uint32_t)*(unsigned short*)&hw << 16) | *(unsigned short*)&hz;
        pl.x = ((uint32_t)*(unsigned short*)&ly << 16) | *(unsigned short*)&lx;
        pl.y = ((uint32_t)*(unsigned short*)&lw << 16) | *(unsigned short*)&lz;
        const int boff = r * A_STRIDE + c4 * 2;
        *(uint2*)(smem + SM_A_HI + boff) = ph;
        *(uint2*)(smem + SM_A_LO + boff) = pl;
    }
    __syncthreads();

    float acc[16][4];
#pragma unroll
    for (int j = 0; j < 16; ++j)
#pragma unroll
        for (int r = 0; r < 4; ++r) acc[j][r] = 0.f;

    const int abase0 = (wid * 16 + g) * A_STRIDE + t * 4;   // row g of this warp
#pragma unroll 1
    for (int pass = 0; pass < 3; ++pass) {
        const char*  ab = smem + ((pass == 2) ? SM_A_LO : SM_A_HI);
        const uint2* wb = (const uint2*)(smem + ((pass == 1) ? SM_W_LO : SM_W_HI));
#pragma unroll
        for (int kk = 0; kk < 8; ++kk) {
            const int ao = abase0 + kk * 32;
            const uint32_t a0 = *(const uint32_t*)(ab + ao);
            const uint32_t a2 = *(const uint32_t*)(ab + ao + 16);
            const uint32_t a1 = *(const uint32_t*)(ab + ao + 8 * A_STRIDE);
            const uint32_t a3 = *(const uint32_t*)(ab + ao + 8 * A_STRIDE + 16);
            const uint2* wrow = wb + kk * 16 * 32 + lane;
#pragma unroll
            for (int j = 0; j < 16; ++j) {
                const uint2 b = wrow[j * 32];
                mma_bf16(acc[j], a0, a1, a2, a3, b.x, b.y);
            }
        }
    }

    // epilogue: rows r0 = rowBase + wid*16 + g, r1 = r0 + 8
    const int r0 = rowBase + wid * 16 + g;
    const int r1 = r0 + 8;
    float ps0[4] = {0, 0, 0, 0}, ps1[4] = {0, 0, 0, 0};
    float pd0[4] = {0, 0, 0, 0}, pd1[4] = {0, 0, 0, 0};
#pragma unroll
    for (int j = 0; j < 16; ++j) {
        const int col = j * 8 + t * 2;
        const int h = j >> 2;
        const float s0 = a_s[col], s1 = a_s[col + 1];
        const float d0 = a_d[col], d1 = a_d[col + 1];
        ps0[h] += acc[j][0] * s0 + acc[j][1] * s1;
        pd0[h] += acc[j][0] * d0 + acc[j][1] * d1;
        ps1[h] += acc[j][2] * s0 + acc[j][3] * s1;
        pd1[h] += acc[j][2] * d0 + acc[j][3] * d1;
        if (r0 < Nn) *(float2*)(hout + (size_t)r0 * 128 + col) = make_float2(acc[j][0], acc[j][1]);
        if (r1 < Nn) *(float2*)(hout + (size_t)r1 * 128 + col) = make_float2(acc[j][2], acc[j][3]);
    }
#pragma unroll
    for (int m = 1; m <= 2; m <<= 1) {
#pragma unroll
        for (int h = 0; h < 4; ++h) {
            ps0[h] += __shfl_xor_sync(0xffffffffu, ps0[h], m);
            ps1[h] += __shfl_xor_sync(0xffffffffu, ps1[h], m);
            pd0[h] += __shfl_xor_sync(0xffffffffu, pd0[h], m);
            pd1[h] += __shfl_xor_sync(0xffffffffu, pd1[h], m);
        }
    }
    if (t == 0) {
        if (r0 < Nn) {
            asout[r0] = make_float4(ps0[0], ps0[1], ps0[2], ps0[3]);
            adout[r0] = make_float4(pd0[0], pd0[1], pd0[2], pd0[3]);
        }
        if (r1 < Nn) {
            asout[r1] = make_float4(ps1[0], ps1[1], ps1[2], ps1[3]);
            adout[r1] = make_float4(pd1[0], pd1[1], pd1[2], pd1[3]);
        }
    }
}

// ---- fused GAT aggregation (unchanged) --------------------------------------
__global__ __launch_bounds__(256)
void k_gat_agg(const float4* __restrict__ h, float4* __restrict__ out,
               const float* __restrict__ bias, int Nn) {
    __shared__ float wsm[8][32][4];
    __shared__ int   ssm[8][32];

    const int warp = (blockIdx.x * 256 + threadIdx.x) >> 5;
    const int lane = threadIdx.x & 31;
    const int w    = threadIdx.x >> 5;
    if (warp >= Nn) return;
    const int v = warp;
    const int head = lane >> 3;

    const float4 adv = g_ad[v];

    float4 acc;
    float  den;
    {
        const float4 asv = g_as[v];
        float4 we;
        we.x = __expf(lrelu(asv.x + adv.x));
        we.y = __expf(lrelu(asv.y + adv.y));
        we.z = __expf(lrelu(asv.z + adv.z));
        we.w = __expf(lrelu(asv.w + adv.w));
        const float wh = (head == 0) ? we.x : (head == 1) ? we.y : (head == 2) ? we.z : we.w;
        const float4 hv = h[(size_t)v * 32 + lane];
        acc = make_float4(hv.x * wh, hv.y * wh, hv.z * wh, hv.w * wh);
        den = wh;
    }

    const int beg = g_rowp[v];
    const int end = g_rowp[v + 1];
    for (int base = beg; base < end; base += 32) {
        int n = end - base; if (n > 32) n = 32;
        int sidx = 0;
        float4 we = make_float4(0.f, 0.f, 0.f, 0.f);
        if (lane < n) {
            sidx = g_csrc[base + lane];
            const float4 s = g_as[sidx];
            we.x = __expf(lrelu(s.x + adv.x));
            we.y = __expf(lrelu(s.y + adv.y));
            we.z = __expf(lrelu(s.z + adv.z));
            we.w = __expf(lrelu(s.w + adv.w));
        }
        ssm[w][lane] = sidx;
        *(float4*)&wsm[w][lane][0] = we;
        __syncwarp();
        for (int j = 0; j < n; ++j) {
            const int   sj = ssm[w][j];
            const float wj = wsm[w][j][head];
            const float4 hv = h[(size_t)sj * 32 + lane];
            acc.x += wj * hv.x;
            acc.y += wj * hv.y;
            acc.z += wj * hv.z;
            acc.w += wj * hv.w;
            den   += wj;
        }
        __syncwarp();
    }

    const float inv = __fdividef(1.f, den);
    const float4 b4 = ((const float4*)bias)[lane];
    float4 o;
    o.x = fmaxf(acc.x * inv + b4.x, 0.f);
    o.y = fmaxf(acc.y * inv + b4.y, 0.f);
    o.z = fmaxf(acc.z * inv + b4.z, 0.f);
    o.w = fmaxf(acc.w * inv + b4.w, 0.f);
    out[(size_t)v * 32 + lane] = o;
}

// ---------------- launch -----------------------------------------------------
extern "C" void kernel_launch(void* const* d_in, const int* in_sizes, int n_in,
                              void* d_out, int out_size) {
    const float* x   = (const float*)d_in[0];
    const void*  ei  = d_in[1];
    const float* W1  = (const float*)d_in[2];
    const float* as1 = (const float*)d_in[3];
    const float* ad1 = (const float*)d_in[4];
    const float* b1  = (const float*)d_in[5];
    const float* W2  = (const float*)d_in[6];
    const float* as2 = (const float*)d_in[7];
    const float* ad2 = (const float*)d_in[8];
    const float* b2  = (const float*)d_in[9];

    const int N  = in_sizes[0] / 128;
    const int E  = in_sizes[1] / 2;

    void* ph = nullptr;   cudaGetSymbolAddress(&ph,  g_h);
    void* po = nullptr;   cudaGetSymbolAddress(&po,  g_out);
    void* pas = nullptr;  cudaGetSymbolAddress(&pas, g_as);
    void* pad = nullptr;  cudaGetSymbolAddress(&pad, g_ad);

    const int ebl = (E + 255) / 256;
    const int nbl = (N + 255) / 256;
    const int abl = (N * 32 + 255) / 256;
    const int gbl = (N + 127) / 128;
    const int sbl = (N + SCAN_CHUNK - 1) / SCAN_CHUNK;

    cudaFuncSetAttribute(k_gemm_mma, cudaFuncAttributeMaxDynamicSharedMemorySize, SMEM_SZ);

    k_detect<<<1, 32>>>((const int*)ei);
    k_wprep<<<128, 256>>>(W1, W2);

    // ---- CSR build ----
    k_zero_deg<<<nbl, 256>>>(N);
    k_hist<<<ebl, 256>>>(ei, E);
    k_blockred<<<sbl, 1024>>>(N);
    k_scanpart<<<1, 32>>>(sbl);
    k_blockscan<<<sbl, 1024>>>(N);
    k_scatter<<<ebl, 256>>>(ei, E);

    // ---- layer 1 ----
    k_gemm_mma<<<gbl, 256, SMEM_SZ>>>(x, 0, as1, ad1, (float*)ph,
                                      (float4*)pas, (float4*)pad, N);
    k_gat_agg<<<abl, 256>>>((const float4*)ph, (float4*)po, b1, N);

    // ---- layer 2 ----
    k_gemm_mma<<<gbl, 256, SMEM_SZ>>>((const float*)po, 1, as2, ad2, (float*)ph,
                                      (float4*)pas, (float4*)pad, N);
    k_gat_agg<<<abl, 256>>>((const float4*)ph, (float4*)d_out, b2, N);
}

// round 6
// speedup vs baseline: 2.8443x; 1.1242x over previous
#include <cuda_runtime.h>
#include <cuda_bf16.h>
#include <cuda_fp16.h>
#include <cstdint>

// Problem shape: N=100000 nodes, E=1600000 edges, D = H*C = 128, H=4, C=32.
#define N_MAX  100000
#define E_MAX  1600000
#define NEG_SLOPE 0.2f
#define SCAN_CHUNK 4096

// ---------------- scratch (device globals) ----------------------------------
__device__ int    g_is64;
__device__ __half g_hh[N_MAX * 128];      // h = x@W in fp16 (gather payload)
__device__ float4 g_as[N_MAX];            // alpha_src per node [N,4]
__device__ float4 g_ad[N_MAX];            // alpha_dst per node [N,4]
__device__ float4 g_out[N_MAX * 32];      // layer-1 output (fp32)
__device__ int    g_deg[N_MAX];
__device__ int    g_rowp[N_MAX + 1];
__device__ int    g_cursor[N_MAX];
__device__ int    g_csrc[E_MAX];
__device__ int    g_part[64];
// W in bf16 hi/lo, pre-packed into mma.m16n8k16 B-fragment order
__device__ unsigned short g_whi[2][16384];
__device__ unsigned short g_wlo[2][16384];

// ---------------- helpers ----------------------------------------------------
__device__ __forceinline__ float lrelu(float x) { return x > 0.f ? x : NEG_SLOPE * x; }

__device__ __forceinline__ int2 get_edge(const void* ei, int e, int E) {
    if (g_is64) {
        const long long* p = (const long long*)ei;
        return make_int2((int)p[e], (int)p[E + e]);
    } else {
        const int* p = (const int*)ei;
        return make_int2(p[e], p[E + e]);
    }
}

__device__ __forceinline__ void mma_bf16(float* c, uint32_t a0, uint32_t a1,
                                         uint32_t a2, uint32_t a3,
                                         uint32_t b0, uint32_t b1) {
    asm volatile(
        "mma.sync.aligned.m16n8k16.row.col.f32.bf16.bf16.f32 "
        "{%0,%1,%2,%3}, {%4,%5,%6,%7}, {%8,%9}, {%0,%1,%2,%3};"
        : "+f"(c[0]), "+f"(c[1]), "+f"(c[2]), "+f"(c[3])
        : "r"(a0), "r"(a1), "r"(a2), "r"(a3), "r"(b0), "r"(b1));
}

// ---------------- misc kernels ----------------------------------------------
__global__ void k_detect(const int* __restrict__ p) {
    if (threadIdx.x == 0 && blockIdx.x == 0) {
        int is64 = 1;
        for (int i = 1; i < 128; i += 2)
            if (p[i] != 0) { is64 = 0; break; }
        g_is64 = is64;
    }
}

__global__ void k_hist(const void* __restrict__ ei, int E) {
    const int e = blockIdx.x * 256 + threadIdx.x;
    if (e >= E) return;
    const int2 sd = get_edge(ei, e, E);
    atomicAdd(&g_deg[sd.y], 1);
}

__global__ __launch_bounds__(1024)
void k_blockred(int Nn) {
    const int t = threadIdx.x;
    const int base = blockIdx.x * SCAN_CHUNK + t * 4;
    int s = 0;
#pragma unroll
    for (int i = 0; i < 4; ++i) {
        const int idx = base + i;
        if (idx < Nn) s += g_deg[idx];
    }
#pragma unroll
    for (int off = 16; off; off >>= 1) s += __shfl_xor_sync(0xffffffffu, s, off);
    __shared__ int wsum[32];
    if ((t & 31) == 0) wsum[t >> 5] = s;
    __syncthreads();
    if (t < 32) {
        int v = wsum[t];
#pragma unroll
        for (int off = 16; off; off >>= 1) v += __shfl_xor_sync(0xffffffffu, v, off);
        if (t == 0) g_part[blockIdx.x] = v;
    }
}

__global__ void k_scanpart(int nparts) {
    if (threadIdx.x == 0) {
        int run = 0;
        for (int i = 0; i < nparts; ++i) {
            const int v = g_part[i];
            g_part[i] = run;
            run += v;
        }
        g_rowp[0] = 0;
    }
}

__global__ __launch_bounds__(1024)
void k_blockscan(int Nn) {
    __shared__ int wsum[32];
    const int t = threadIdx.x;
    const int lane = t & 31;
    const int wid  = t >> 5;
    const int base = blockIdx.x * SCAN_CHUNK + t * 4;

    int vals[4];
    int local = 0;
#pragma unroll
    for (int i = 0; i < 4; ++i) {
        const int idx = base + i;
        vals[i] = (idx < Nn) ? g_deg[idx] : 0;
        local += vals[i];
    }
    int x = local;
#pragma unroll
    for (int off = 1; off < 32; off <<= 1) {
        const int n = __shfl_up_sync(0xffffffffu, x, off);
        if (lane >= off) x += n;
    }
    if (lane == 31) wsum[wid] = x;
    __syncthreads();
    if (wid == 0) {
        int v = wsum[lane];
#pragma unroll
        for (int off = 1; off < 32; off <<= 1) {
            const int n = __shfl_up_sync(0xffffffffu, v, off);
            if (lane >= off) v += n;
        }
        wsum[lane] = v;
    }
    __syncthreads();
    const int warpoff = (wid > 0) ? wsum[wid - 1] : 0;
    int run = g_part[blockIdx.x] + warpoff + (x - local);
#pragma unroll
    for (int i = 0; i < 4; ++i) {
        const int idx = base + i;
        if (idx < Nn) {
            g_cursor[idx]   = run;
            g_rowp[idx + 1] = run + vals[i];
        }
        run += vals[i];
    }
}

__global__ void k_scatter(const void* __restrict__ ei, int E) {
    const int e = blockIdx.x * 256 + threadIdx.x;
    if (e >= E) return;
    const int2 sd = get_edge(ei, e, E);
    const int pos = atomicAdd(&g_cursor[sd.y], 1);
    g_csrc[pos] = sd.x;
}

// ---- W prep: fp32 W[k,n] -> bf16 hi/lo in per-lane mma B-fragment order ----
__global__ void k_wprep(const float* __restrict__ W1, const float* __restrict__ W2) {
    const int idx = blockIdx.x * 256 + threadIdx.x;
    if (idx >= 32768) return;
    const int layer = idx >> 14;
    const int e = idx & 16383;
    const int k = e >> 7, n = e & 127;
    const float w = (layer ? W2 : W1)[k * 128 + n];
    __nv_bfloat16 hi = __float2bfloat16(w);
    __nv_bfloat16 lo = __float2bfloat16(w - __bfloat162float(hi));
    const int kk = k >> 4, kin = k & 15;
    const int reg = kin >> 3, t = (kin & 7) >> 1, half = kin & 1;
    const int j = n >> 3, g = n & 7;
    const int lane = g * 4 + t;
    const int off = ((kk * 16 + j) * 32 + lane) * 4 + reg * 2 + half;
    g_whi[layer][off] = *(unsigned short*)&hi;
    g_wlo[layer][off] = *(unsigned short*)&lo;
}

// ---- HMMA GEMM via mma.sync: 128-row tile per block (8 warps x 16 rows).
// D = Ahi*Bhi + Ahi*Blo + Alo*Bhi. Epilogue: h in fp16 + fused alpha projections.
#define SM_A_HI 0
#define SM_A_LO 34816
#define SM_W_HI 69632
#define SM_W_LO 102400
#define SMEM_SZ 135168
#define A_STRIDE 272   // bytes per A smem row (136 bf16) - conflict-free

__global__ __launch_bounds__(256, 1)
void k_gemm_mma(const float* __restrict__ A, int layer,
                const float* __restrict__ a_s, const float* __restrict__ a_d,
                __half* __restrict__ hout, float4* __restrict__ asout,
                float4* __restrict__ adout, int Nn) {
    extern __shared__ __align__(16) char smem[];
    const int tid  = threadIdx.x;
    const int lane = tid & 31;
    const int wid  = tid >> 5;
    const int g    = lane >> 2;
    const int t    = lane & 3;
    const int rowBase = blockIdx.x * 128;

    {
        const uint4* shi = (const uint4*)g_whi[layer];
        const uint4* slo = (const uint4*)g_wlo[layer];
        uint4* dhi = (uint4*)(smem + SM_W_HI);
        uint4* dlo = (uint4*)(smem + SM_W_LO);
        for (int i = tid; i < 2048; i += 256) { dhi[i] = shi[i]; dlo[i] = slo[i]; }
    }
    for (int idx = tid; idx < 4096; idx += 256) {
        const int r = idx >> 5;
        const int c4 = (idx & 31) * 4;
        int row = rowBase + r;
        if (row >= Nn) row = Nn - 1;
        const float4 v = *(const float4*)(A + (size_t)row * 128 + c4);
        __nv_bfloat16 hx = __float2bfloat16(v.x), hy = __float2bfloat16(v.y);
        __nv_bfloat16 hz = __float2bfloat16(v.z), hw = __float2bfloat16(v.w);
        __nv_bfloat16 lx = __float2bfloat16(v.x - __bfloat162float(hx));
        __nv_bfloat16 ly = __float2bfloat16(v.y - __bfloat162float(hy));
        __nv_bfloat16 lz = __float2bfloat16(v.z - __bfloat162float(hz));
        __nv_bfloat16 lw = __float2bfloat16(v.w - __bfloat162float(hw));
        uint2 ph, pl;
        ph.x = ((uint32_t)*(unsigned short*)&hy << 16) | *(unsigned short*)&hx;
        ph.y = ((uint32_t)*(unsigned short*)&hw << 16) | *(unsigned short*)&hz;
        pl.x = ((uint32_t)*(unsigned short*)&ly << 16) | *(unsigned short*)&lx;
        pl.y = ((uint32_t)*(unsigned short*)&lw << 16) | *(unsigned short*)&lz;
        const int boff = r * A_STRIDE + c4 * 2;
        *(uint2*)(smem + SM_A_HI + boff) = ph;
        *(uint2*)(smem + SM_A_LO + boff) = pl;
    }
    __syncthreads();

    float acc[16][4];
#pragma unroll
    for (int j = 0; j < 16; ++j)
#pragma unroll
        for (int r = 0; r < 4; ++r) acc[j][r] = 0.f;

    const int abase0 = (wid * 16 + g) * A_STRIDE + t * 4;
#pragma unroll 1
    for (int pass = 0; pass < 3; ++pass) {
        const char*  ab = smem + ((pass == 2) ? SM_A_LO : SM_A_HI);
        const uint2* wb = (const uint2*)(smem + ((pass == 1) ? SM_W_LO : SM_W_HI));
#pragma unroll
        for (int kk = 0; kk < 8; ++kk) {
            const int ao = abase0 + kk * 32;
            const uint32_t a0 = *(const uint32_t*)(ab + ao);
            const uint32_t a2 = *(const uint32_t*)(ab + ao + 16);
            const uint32_t a1 = *(const uint32_t*)(ab + ao + 8 * A_STRIDE);
            const uint32_t a3 = *(const uint32_t*)(ab + ao + 8 * A_STRIDE + 16);
            const uint2* wrow = wb + kk * 16 * 32 + lane;
#pragma unroll
            for (int j = 0; j < 16; ++j) {
                const uint2 b = wrow[j * 32];
                mma_bf16(acc[j], a0, a1, a2, a3, b.x, b.y);
            }
        }
    }

    // epilogue: rows r0 = rowBase + wid*16 + g, r1 = r0 + 8; h stored fp16
    const int r0 = rowBase + wid * 16 + g;
    const int r1 = r0 + 8;
    float ps0[4] = {0, 0, 0, 0}, ps1[4] = {0, 0, 0, 0};
    float pd0[4] = {0, 0, 0, 0}, pd1[4] = {0, 0, 0, 0};
#pragma unroll
    for (int j = 0; j < 16; ++j) {
        const int col = j * 8 + t * 2;
        const int h = j >> 2;
        const float s0 = a_s[col], s1 = a_s[col + 1];
        const float d0 = a_d[col], d1 = a_d[col + 1];
        ps0[h] += acc[j][0] * s0 + acc[j][1] * s1;
        pd0[h] += acc[j][0] * d0 + acc[j][1] * d1;
        ps1[h] += acc[j][2] * s0 + acc[j][3] * s1;
        pd1[h] += acc[j][2] * d0 + acc[j][3] * d1;
        if (r0 < Nn) *(__half2*)(hout + (size_t)r0 * 128 + col) = __floats2half2_rn(acc[j][0], acc[j][1]);
        if (r1 < Nn) *(__half2*)(hout + (size_t)r1 * 128 + col) = __floats2half2_rn(acc[j][2], acc[j][3]);
    }
#pragma unroll
    for (int m = 1; m <= 2; m <<= 1) {
#pragma unroll
        for (int h = 0; h < 4; ++h) {
            ps0[h] += __shfl_xor_sync(0xffffffffu, ps0[h], m);
            ps1[h] += __shfl_xor_sync(0xffffffffu, ps1[h], m);
            pd0[h] += __shfl_xor_sync(0xffffffffu, pd0[h], m);
            pd1[h] += __shfl_xor_sync(0xffffffffu, pd1[h], m);
        }
    }
    if (t == 0) {
        if (r0 < Nn) {
            asout[r0] = make_float4(ps0[0], ps0[1], ps0[2], ps0[3]);
            adout[r0] = make_float4(pd0[0], pd0[1], pd0[2], pd0[3]);
        }
        if (r1 < Nn) {
            asout[r1] = make_float4(ps1[0], ps1[1], ps1[2], ps1[3]);
            adout[r1] = make_float4(pd1[0], pd1[1], pd1[2], pd1[3]);
        }
    }
}

// ---- fused GAT aggregation: one warp per dst node, fp16 h gather ------------
__global__ __launch_bounds__(256)
void k_gat_agg(const __half* __restrict__ h, float4* __restrict__ out,
               const float* __restrict__ bias, int Nn) {
    __shared__ float wsm[8][32][4];
    __shared__ int   ssm[8][32];

    const int warp = (blockIdx.x * 256 + threadIdx.x) >> 5;
    const int lane = threadIdx.x & 31;
    const int w    = threadIdx.x >> 5;
    if (warp >= Nn) return;
    const int v = warp;
    const int head = lane >> 3;

    const float4 adv = g_ad[v];

    float4 acc;
    float  den;
    {
        const float4 asv = g_as[v];
        float4 we;
        we.x = __expf(lrelu(asv.x + adv.x));
        we.y = __expf(lrelu(asv.y + adv.y));
        we.z = __expf(lrelu(asv.z + adv.z));
        we.w = __expf(lrelu(asv.w + adv.w));
        const float wh = (head == 0) ? we.x : (head == 1) ? we.y : (head == 2) ? we.z : we.w;
        const uint2 hv = ((const uint2*)(h + (size_t)v * 128))[lane];
        const float2 p0 = __half22float2(*(const __half2*)&hv.x);
        const float2 p1 = __half22float2(*(const __half2*)&hv.y);
        acc = make_float4(p0.x * wh, p0.y * wh, p1.x * wh, p1.y * wh);
        den = wh;
    }

    const int beg = g_rowp[v];
    const int end = g_rowp[v + 1];
    for (int base = beg; base < end; base += 32) {
        int n = end - base; if (n > 32) n = 32;
        int sidx = 0;
        float4 we = make_float4(0.f, 0.f, 0.f, 0.f);
        if (lane < n) {
            sidx = g_csrc[base + lane];
            const float4 s = g_as[sidx];
            we.x = __expf(lrelu(s.x + adv.x));
            we.y = __expf(lrelu(s.y + adv.y));
            we.z = __expf(lrelu(s.z + adv.z));
            we.w = __expf(lrelu(s.w + adv.w));
        }
        ssm[w][lane] = sidx;
        *(float4*)&wsm[w][lane][0] = we;
        __syncwarp();
        for (int j = 0; j < n; ++j) {
            const int   sj = ssm[w][j];
            const float wj = wsm[w][j][head];
            const uint2 hv = ((const uint2*)(h + (size_t)sj * 128))[lane];
            const float2 p0 = __half22float2(*(const __half2*)&hv.x);
            const float2 p1 = __half22float2(*(const __half2*)&hv.y);
            acc.x += wj * p0.x;
            acc.y += wj * p0.y;
            acc.z += wj * p1.x;
            acc.w += wj * p1.y;
            den   += wj;
        }
        __syncwarp();
    }

    const float inv = __fdividef(1.f, den);
    const float4 b4 = ((const float4*)bias)[lane];
    float4 o;
    o.x = fmaxf(acc.x * inv + b4.x, 0.f);
    o.y = fmaxf(acc.y * inv + b4.y, 0.f);
    o.z = fmaxf(acc.z * inv + b4.z, 0.f);
    o.w = fmaxf(acc.w * inv + b4.w, 0.f);
    out[(size_t)v * 32 + lane] = o;
}

// ---------------- launch -----------------------------------------------------
extern "C" void kernel_launch(void* const* d_in, const int* in_sizes, int n_in,
                              void* d_out, int out_size) {
    const float* x   = (const float*)d_in[0];
    const void*  ei  = d_in[1];
    const float* W1  = (const float*)d_in[2];
    const float* as1 = (const float*)d_in[3];
    const float* ad1 = (const float*)d_in[4];
    const float* b1  = (const float*)d_in[5];
    const float* W2  = (const float*)d_in[6];
    const float* as2 = (const float*)d_in[7];
    const float* ad2 = (const float*)d_in[8];
    const float* b2  = (const float*)d_in[9];

    const int N  = in_sizes[0] / 128;
    const int E  = in_sizes[1] / 2;

    void* ph = nullptr;   cudaGetSymbolAddress(&ph,  g_hh);
    void* po = nullptr;   cudaGetSymbolAddress(&po,  g_out);
    void* pas = nullptr;  cudaGetSymbolAddress(&pas, g_as);
    void* pad = nullptr;  cudaGetSymbolAddress(&pad, g_ad);
    void* pdeg = nullptr; cudaGetSymbolAddress(&pdeg, g_deg);

    const int ebl = (E + 255) / 256;
    const int abl = (N * 32 + 255) / 256;
    const int gbl = (N + 127) / 128;
    const int sbl = (N + SCAN_CHUNK - 1) / SCAN_CHUNK;

    cudaFuncSetAttribute(k_gemm_mma, cudaFuncAttributeMaxDynamicSharedMemorySize, SMEM_SZ);

    k_detect<<<1, 32>>>((const int*)ei);
    k_wprep<<<128, 256>>>(W1, W2);

    // ---- CSR build ----
    cudaMemsetAsync(pdeg, 0, N * sizeof(int));
    k_hist<<<ebl, 256>>>(ei, E);
    k_blockred<<<sbl, 1024>>>(N);
    k_scanpart<<<1, 32>>>(sbl);
    k_blockscan<<<sbl, 1024>>>(N);
    k_scatter<<<ebl, 256>>>(ei, E);

    // ---- layer 1 ----
    k_gemm_mma<<<gbl, 256, SMEM_SZ>>>(x, 0, as1, ad1, (__half*)ph,
                                      (float4*)pas, (float4*)pad, N);
    k_gat_agg<<<abl, 256>>>((const __half*)ph, (float4*)po, b1, N);

    // ---- layer 2 ----
    k_gemm_mma<<<gbl, 256, SMEM_SZ>>>((const float*)po, 1, as2, ad2, (__half*)ph,
                                      (float4*)pas, (float4*)pad, N);
    k_gat_agg<<<abl, 256>>>((const __half*)ph, (float4*)d_out, b2, N);
}

// round 7
// speedup vs baseline: 3.1273x; 1.0995x over previous
#include <cuda_runtime.h>
#include <cuda_bf16.h>
#include <cuda_fp16.h>
#include <cstdint>

// Problem shape: N=100000 nodes, E=1600000 edges, D = H*C = 128, H=4, C=32.
#define N_MAX  100000
#define E_MAX  1600000
#define NEG_SLOPE 0.2f
#define SCAN_CHUNK 4096

// ---------------- scratch (device globals) ----------------------------------
__device__ int    g_is64;
__device__ __half g_hh[N_MAX * 128];      // h = x@W in fp16 (gather payload)
__device__ float4 g_as[N_MAX];            // alpha_src per node [N,4]
__device__ float4 g_ad[N_MAX];            // alpha_dst per node [N,4]
__device__ float4 g_out[N_MAX * 32];      // layer-1 output (fp32)
__device__ int    g_deg[N_MAX];
__device__ int    g_rowp[N_MAX + 1];
__device__ int    g_cursor[N_MAX];
__device__ int    g_csrc[E_MAX];
__device__ int    g_part[64];
// W in bf16 hi/lo, pre-packed into mma.m16n8k16 B-fragment order
__device__ unsigned short g_whi[2][16384];
__device__ unsigned short g_wlo[2][16384];

// ---------------- helpers ----------------------------------------------------
__device__ __forceinline__ float lrelu(float x) { return x > 0.f ? x : NEG_SLOPE * x; }

__device__ __forceinline__ int2 get_edge(const void* ei, int e, int E) {
    if (g_is64) {
        const long long* p = (const long long*)ei;
        return make_int2((int)p[e], (int)p[E + e]);
    } else {
        const int* p = (const int*)ei;
        return make_int2(p[e], p[E + e]);
    }
}

__device__ __forceinline__ void mma_bf16(float* c, uint32_t a0, uint32_t a1,
                                         uint32_t a2, uint32_t a3,
                                         uint32_t b0, uint32_t b1) {
    asm volatile(
        "mma.sync.aligned.m16n8k16.row.col.f32.bf16.bf16.f32 "
        "{%0,%1,%2,%3}, {%4,%5,%6,%7}, {%8,%9}, {%0,%1,%2,%3};"
        : "+f"(c[0]), "+f"(c[1]), "+f"(c[2]), "+f"(c[3])
        : "r"(a0), "r"(a1), "r"(a2), "r"(a3), "r"(b0), "r"(b1));
}

// ---------------- misc kernels ----------------------------------------------
__global__ void k_detect(const int* __restrict__ p) {
    if (threadIdx.x == 0 && blockIdx.x == 0) {
        int is64 = 1;
        for (int i = 1; i < 128; i += 2)
            if (p[i] != 0) { is64 = 0; break; }
        g_is64 = is64;
    }
}

__global__ void k_hist(const void* __restrict__ ei, int E) {
    const int e = blockIdx.x * 256 + threadIdx.x;
    if (e >= E) return;
    const int2 sd = get_edge(ei, e, E);
    atomicAdd(&g_deg[sd.y], 1);
}

__global__ __launch_bounds__(1024)
void k_blockred(int Nn) {
    const int t = threadIdx.x;
    const int base = blockIdx.x * SCAN_CHUNK + t * 4;
    int s = 0;
#pragma unroll
    for (int i = 0; i < 4; ++i) {
        const int idx = base + i;
        if (idx < Nn) s += g_deg[idx];
    }
#pragma unroll
    for (int off = 16; off; off >>= 1) s += __shfl_xor_sync(0xffffffffu, s, off);
    __shared__ int wsum[32];
    if ((t & 31) == 0) wsum[t >> 5] = s;
    __syncthreads();
    if (t < 32) {
        int v = wsum[t];
#pragma unroll
        for (int off = 16; off; off >>= 1) v += __shfl_xor_sync(0xffffffffu, v, off);
        if (t == 0) g_part[blockIdx.x] = v;
    }
}

__global__ void k_scanpart(int nparts) {
    if (threadIdx.x == 0) {
        int run = 0;
        for (int i = 0; i < nparts; ++i) {
            const int v = g_part[i];
            g_part[i] = run;
            run += v;
        }
        g_rowp[0] = 0;
    }
}

__global__ __launch_bounds__(1024)
void k_blockscan(int Nn) {
    __shared__ int wsum[32];
    const int t = threadIdx.x;
    const int lane = t & 31;
    const int wid  = t >> 5;
    const int base = blockIdx.x * SCAN_CHUNK + t * 4;

    int vals[4];
    int local = 0;
#pragma unroll
    for (int i = 0; i < 4; ++i) {
        const int idx = base + i;
        vals[i] = (idx < Nn) ? g_deg[idx] : 0;
        local += vals[i];
    }
    int x = local;
#pragma unroll
    for (int off = 1; off < 32; off <<= 1) {
        const int n = __shfl_up_sync(0xffffffffu, x, off);
        if (lane >= off) x += n;
    }
    if (lane == 31) wsum[wid] = x;
    __syncthreads();
    if (wid == 0) {
        int v = wsum[lane];
#pragma unroll
        for (int off = 1; off < 32; off <<= 1) {
            const int n = __shfl_up_sync(0xffffffffu, v, off);
            if (lane >= off) v += n;
        }
        wsum[lane] = v;
    }
    __syncthreads();
    const int warpoff = (wid > 0) ? wsum[wid - 1] : 0;
    int run = g_part[blockIdx.x] + warpoff + (x - local);
#pragma unroll
    for (int i = 0; i < 4; ++i) {
        const int idx = base + i;
        if (idx < Nn) {
            g_cursor[idx]   = run;
            g_rowp[idx + 1] = run + vals[i];
        }
        run += vals[i];
    }
}

__global__ void k_scatter(const void* __restrict__ ei, int E) {
    const int e = blockIdx.x * 256 + threadIdx.x;
    if (e >= E) return;
    const int2 sd = get_edge(ei, e, E);
    const int pos = atomicAdd(&g_cursor[sd.y], 1);
    g_csrc[pos] = sd.x;
}

// ---- W prep: fp32 W[k,n] -> bf16 hi/lo in per-lane mma B-fragment order ----
__global__ void k_wprep(const float* __restrict__ W1, const float* __restrict__ W2) {
    const int idx = blockIdx.x * 256 + threadIdx.x;
    if (idx >= 32768) return;
    const int layer = idx >> 14;
    const int e = idx & 16383;
    const int k = e >> 7, n = e & 127;
    const float w = (layer ? W2 : W1)[k * 128 + n];
    __nv_bfloat16 hi = __float2bfloat16(w);
    __nv_bfloat16 lo = __float2bfloat16(w - __bfloat162float(hi));
    const int kk = k >> 4, kin = k & 15;
    const int reg = kin >> 3, t = (kin & 7) >> 1, half = kin & 1;
    const int j = n >> 3, g = n & 7;
    const int lane = g * 4 + t;
    const int off = ((kk * 16 + j) * 32 + lane) * 4 + reg * 2 + half;
    g_whi[layer][off] = *(unsigned short*)&hi;
    g_wlo[layer][off] = *(unsigned short*)&lo;
}

// ---- HMMA GEMM via mma.sync: 128-row tile per block (8 warps x 16 rows).
// Fused sweep: per (kk,j) load Bhi/Blo once, issue Ahi*Bhi + Ahi*Blo + Alo*Bhi.
#define SM_A_HI 0
#define SM_A_LO 34816
#define SM_W_HI 69632
#define SM_W_LO 102400
#define SMEM_SZ 135168
#define A_STRIDE 272   // bytes per A smem row (136 bf16) - conflict-free

__global__ __launch_bounds__(256, 1)
void k_gemm_mma(const float* __restrict__ A, int layer,
                const float* __restrict__ a_s, const float* __restrict__ a_d,
                __half* __restrict__ hout, float4* __restrict__ asout,
                float4* __restrict__ adout, int Nn) {
    extern __shared__ __align__(16) char smem[];
    const int tid  = threadIdx.x;
    const int lane = tid & 31;
    const int wid  = tid >> 5;
    const int g    = lane >> 2;
    const int t    = lane & 3;
    const int rowBase = blockIdx.x * 128;

    {
        const uint4* shi = (const uint4*)g_whi[layer];
        const uint4* slo = (const uint4*)g_wlo[layer];
        uint4* dhi = (uint4*)(smem + SM_W_HI);
        uint4* dlo = (uint4*)(smem + SM_W_LO);
        for (int i = tid; i < 2048; i += 256) { dhi[i] = shi[i]; dlo[i] = slo[i]; }
    }
    for (int idx = tid; idx < 4096; idx += 256) {
        const int r = idx >> 5;
        const int c4 = (idx & 31) * 4;
        int row = rowBase + r;
        if (row >= Nn) row = Nn - 1;
        const float4 v = *(const float4*)(A + (size_t)row * 128 + c4);
        __nv_bfloat16 hx = __float2bfloat16(v.x), hy = __float2bfloat16(v.y);
        __nv_bfloat16 hz = __float2bfloat16(v.z), hw = __float2bfloat16(v.w);
        __nv_bfloat16 lx = __float2bfloat16(v.x - __bfloat162float(hx));
        __nv_bfloat16 ly = __float2bfloat16(v.y - __bfloat162float(hy));
        __nv_bfloat16 lz = __float2bfloat16(v.z - __bfloat162float(hz));
        __nv_bfloat16 lw = __float2bfloat16(v.w - __bfloat162float(hw));
        uint2 ph, pl;
        ph.x = ((uint32_t)*(unsigned short*)&hy << 16) | *(unsigned short*)&hx;
        ph.y = ((uint32_t)*(unsigned short*)&hw << 16) | *(unsigned short*)&hz;
        pl.x = ((uint32_t)*(unsigned short*)&ly << 16) | *(unsigned short*)&lx;
        pl.y = ((uint32_t)*(unsigned short*)&lw << 16) | *(unsigned short*)&lz;
        const int boff = r * A_STRIDE + c4 * 2;
        *(uint2*)(smem + SM_A_HI + boff) = ph;
        *(uint2*)(smem + SM_A_LO + boff) = pl;
    }
    __syncthreads();

    float acc[16][4];
#pragma unroll
    for (int j = 0; j < 16; ++j)
#pragma unroll
        for (int r = 0; r < 4; ++r) acc[j][r] = 0.f;

    const int abase0 = (wid * 16 + g) * A_STRIDE + t * 4;
#pragma unroll
    for (int kk = 0; kk < 8; ++kk) {
        const int ao = abase0 + kk * 32;
        const uint32_t ah0 = *(const uint32_t*)(smem + SM_A_HI + ao);
        const uint32_t ah2 = *(const uint32_t*)(smem + SM_A_HI + ao + 16);
        const uint32_t ah1 = *(const uint32_t*)(smem + SM_A_HI + ao + 8 * A_STRIDE);
        const uint32_t ah3 = *(const uint32_t*)(smem + SM_A_HI + ao + 8 * A_STRIDE + 16);
        const uint32_t al0 = *(const uint32_t*)(smem + SM_A_LO + ao);
        const uint32_t al2 = *(const uint32_t*)(smem + SM_A_LO + ao + 16);
        const uint32_t al1 = *(const uint32_t*)(smem + SM_A_LO + ao + 8 * A_STRIDE);
        const uint32_t al3 = *(const uint32_t*)(smem + SM_A_LO + ao + 8 * A_STRIDE + 16);
        const uint2* whrow = (const uint2*)(smem + SM_W_HI) + kk * 512 + lane;
        const uint2* wlrow = (const uint2*)(smem + SM_W_LO) + kk * 512 + lane;
#pragma unroll
        for (int j = 0; j < 16; ++j) {
            const uint2 bh = whrow[j * 32];
            const uint2 bl = wlrow[j * 32];
            mma_bf16(acc[j], ah0, ah1, ah2, ah3, bh.x, bh.y);
            mma_bf16(acc[j], ah0, ah1, ah2, ah3, bl.x, bl.y);
            mma_bf16(acc[j], al0, al1, al2, al3, bh.x, bh.y);
        }
    }

    // epilogue: rows r0 = rowBase + wid*16 + g, r1 = r0 + 8; h stored fp16
    const int r0 = rowBase + wid * 16 + g;
    const int r1 = r0 + 8;
    float ps0[4] = {0, 0, 0, 0}, ps1[4] = {0, 0, 0, 0};
    float pd0[4] = {0, 0, 0, 0}, pd1[4] = {0, 0, 0, 0};
#pragma unroll
    for (int j = 0; j < 16; ++j) {
        const int col = j * 8 + t * 2;
        const int h = j >> 2;
        const float s0 = a_s[col], s1 = a_s[col + 1];
        const float d0 = a_d[col], d1 = a_d[col + 1];
        ps0[h] += acc[j][0] * s0 + acc[j][1] * s1;
        pd0[h] += acc[j][0] * d0 + acc[j][1] * d1;
        ps1[h] += acc[j][2] * s0 + acc[j][3] * s1;
        pd1[h] += acc[j][2] * d0 + acc[j][3] * d1;
        if (r0 < Nn) *(__half2*)(hout + (size_t)r0 * 128 + col) = __floats2half2_rn(acc[j][0], acc[j][1]);
        if (r1 < Nn) *(__half2*)(hout + (size_t)r1 * 128 + col) = __floats2half2_rn(acc[j][2], acc[j][3]);
    }
#pragma unroll
    for (int m = 1; m <= 2; m <<= 1) {
#pragma unroll
        for (int h = 0; h < 4; ++h) {
            ps0[h] += __shfl_xor_sync(0xffffffffu, ps0[h], m);
            ps1[h] += __shfl_xor_sync(0xffffffffu, ps1[h], m);
            pd0[h] += __shfl_xor_sync(0xffffffffu, pd0[h], m);
            pd1[h] += __shfl_xor_sync(0xffffffffu, pd1[h], m);
        }
    }
    if (t == 0) {
        if (r0 < Nn) {
            asout[r0] = make_float4(ps0[0], ps0[1], ps0[2], ps0[3]);
            adout[r0] = make_float4(pd0[0], pd0[1], pd0[2], pd0[3]);
        }
        if (r1 < Nn) {
            asout[r1] = make_float4(ps1[0], ps1[1], ps1[2], ps1[3]);
            adout[r1] = make_float4(pd1[0], pd1[1], pd1[2], pd1[3]);
        }
    }
}

// ---- fused GAT aggregation: one warp per dst node, fp16 h gather ------------
__global__ __launch_bounds__(256)
void k_gat_agg(const __half* __restrict__ h, float4* __restrict__ out,
               const float* __restrict__ bias, int Nn) {
    __shared__ float wsm[8][32][4];
    __shared__ int   ssm[8][32];

    const int warp = (blockIdx.x * 256 + threadIdx.x) >> 5;
    const int lane = threadIdx.x & 31;
    const int w    = threadIdx.x >> 5;
    if (warp >= Nn) return;
    const int v = warp;
    const int head = lane >> 3;

    const float4 adv = g_ad[v];

    float4 acc;
    float  den;
    {
        const float4 asv = g_as[v];
        float4 we;
        we.x = __expf(lrelu(asv.x + adv.x));
        we.y = __expf(lrelu(asv.y + adv.y));
        we.z = __expf(lrelu(asv.z + adv.z));
        we.w = __expf(lrelu(asv.w + adv.w));
        const float wh = (head == 0) ? we.x : (head == 1) ? we.y : (head == 2) ? we.z : we.w;
        const uint2 hv = ((const uint2*)(h + (size_t)v * 128))[lane];
        const float2 p0 = __half22float2(*(const __half2*)&hv.x);
        const float2 p1 = __half22float2(*(const __half2*)&hv.y);
        acc = make_float4(p0.x * wh, p0.y * wh, p1.x * wh, p1.y * wh);
        den = wh;
    }

    const int beg = g_rowp[v];
    const int end = g_rowp[v + 1];
    for (int base = beg; base < end; base += 32) {
        int n = end - base; if (n > 32) n = 32;
        int sidx = 0;
        float4 we = make_float4(0.f, 0.f, 0.f, 0.f);
        if (lane < n) {
            sidx = g_csrc[base + lane];
            const float4 s = g_as[sidx];
            we.x = __expf(lrelu(s.x + adv.x));
            we.y = __expf(lrelu(s.y + adv.y));
            we.z = __expf(lrelu(s.z + adv.z));
            we.w = __expf(lrelu(s.w + adv.w));
        }
        ssm[w][lane] = sidx;
        *(float4*)&wsm[w][lane][0] = we;
        __syncwarp();
        for (int j = 0; j < n; ++j) {
            const int   sj = ssm[w][j];
            const float wj = wsm[w][j][head];
            const uint2 hv = ((const uint2*)(h + (size_t)sj * 128))[lane];
            const float2 p0 = __half22float2(*(const __half2*)&hv.x);
            const float2 p1 = __half22float2(*(const __half2*)&hv.y);
            acc.x += wj * p0.x;
            acc.y += wj * p0.y;
            acc.z += wj * p1.x;
            acc.w += wj * p1.y;
            den   += wj;
        }
        __syncwarp();
    }

    const float inv = __fdividef(1.f, den);
    const float4 b4 = ((const float4*)bias)[lane];
    float4 o;
    o.x = fmaxf(acc.x * inv + b4.x, 0.f);
    o.y = fmaxf(acc.y * inv + b4.y, 0.f);
    o.z = fmaxf(acc.z * inv + b4.z, 0.f);
    o.w = fmaxf(acc.w * inv + b4.w, 0.f);
    out[(size_t)v * 32 + lane] = o;
}

// ---------------- launch -----------------------------------------------------
extern "C" void kernel_launch(void* const* d_in, const int* in_sizes, int n_in,
                              void* d_out, int out_size) {
    const float* x   = (const float*)d_in[0];
    const void*  ei  = d_in[1];
    const float* W1  = (const float*)d_in[2];
    const float* as1 = (const float*)d_in[3];
    const float* ad1 = (const float*)d_in[4];
    const float* b1  = (const float*)d_in[5];
    const float* W2  = (const float*)d_in[6];
    const float* as2 = (const float*)d_in[7];
    const float* ad2 = (const float*)d_in[8];
    const float* b2  = (const float*)d_in[9];

    const int N  = in_sizes[0] / 128;
    const int E  = in_sizes[1] / 2;

    void* ph = nullptr;   cudaGetSymbolAddress(&ph,  g_hh);
    void* po = nullptr;   cudaGetSymbolAddress(&po,  g_out);
    void* pas = nullptr;  cudaGetSymbolAddress(&pas, g_as);
    void* pad = nullptr;  cudaGetSymbolAddress(&pad, g_ad);
    void* pdeg = nullptr; cudaGetSymbolAddress(&pdeg, g_deg);

    const int ebl = (E + 255) / 256;
    const int abl = (N * 32 + 255) / 256;
    const int gbl = (N + 127) / 128;
    const int sbl = (N + SCAN_CHUNK - 1) / SCAN_CHUNK;

    cudaFuncSetAttribute(k_gemm_mma, cudaFuncAttributeMaxDynamicSharedMemorySize, SMEM_SZ);

    // side stream + fork/join events (created once; graph shape is identical
    // on every call, so capture and replay are deterministic)
    static cudaStream_t s2 = nullptr;
    static cudaEvent_t evFork = nullptr, evJoin = nullptr;
    if (!s2) {
        cudaStreamCreateWithFlags(&s2, cudaStreamNonBlocking);
        cudaEventCreateWithFlags(&evFork, cudaEventDisableTiming);
        cudaEventCreateWithFlags(&evJoin, cudaEventDisableTiming);
    }

    k_detect<<<1, 32>>>((const int*)ei);

    // ---- fork: CSR build on s2, concurrent with W prep + layer-1 GEMM ----
    cudaEventRecord(evFork, 0);
    cudaStreamWaitEvent(s2, evFork, 0);

    cudaMemsetAsync(pdeg, 0, N * sizeof(int), s2);
    k_hist<<<ebl, 256, 0, s2>>>(ei, E);
    k_blockred<<<sbl, 1024, 0, s2>>>(N);
    k_scanpart<<<1, 32, 0, s2>>>(sbl);
    k_blockscan<<<sbl, 1024, 0, s2>>>(N);
    k_scatter<<<ebl, 256, 0, s2>>>(ei, E);
    cudaEventRecord(evJoin, s2);

    // ---- main stream: layer-1 GEMM ----
    k_wprep<<<128, 256>>>(W1, W2);
    k_gemm_mma<<<gbl, 256, SMEM_SZ>>>(x, 0, as1, ad1, (__half*)ph,
                                      (float4*)pas, (float4*)pad, N);

    // ---- join: aggregation needs both CSR and GEMM-1 ----
    cudaStreamWaitEvent(0, evJoin, 0);
    k_gat_agg<<<abl, 256>>>((const __half*)ph, (float4*)po, b1, N);

    // ---- layer 2 ----
    k_gemm_mma<<<gbl, 256, SMEM_SZ>>>((const float*)po, 1, as2, ad2, (__half*)ph,
                                      (float4*)pas, (float4*)pad, N);
    k_gat_agg<<<abl, 256>>>((const __half*)ph, (float4*)d_out, b2, N);
}

// round 8
// speedup vs baseline: 3.5830x; 1.1457x over previous
#include <cuda_runtime.h>
#include <cuda_bf16.h>
#include <cuda_fp16.h>
#include <cstdint>

// Problem shape: N=100000 nodes, E=1600000 edges, D = H*C = 128, H=4, C=32.
#define N_MAX  100000
#define E_MAX  1600000
#define NEG_SLOPE 0.2f
#define SCAN_CHUNK 4096

// ---------------- scratch (device globals) ----------------------------------
__device__ int    g_is64;
__device__ __half g_hh[N_MAX * 128];      // h = x@W in fp16 (gather payload)
__device__ float4 g_as[N_MAX];            // alpha_src per node [N,4]
__device__ float4 g_ad[N_MAX];            // alpha_dst per node [N,4]
__device__ float4 g_out[N_MAX * 32];      // layer-1 output (fp32)
__device__ int    g_deg[N_MAX];
__device__ int    g_rowp[N_MAX + 1];
__device__ int    g_cursor[N_MAX];
__device__ int    g_csrc[E_MAX];
__device__ int    g_part[64];
// W split into fp16 hi/lo, pre-packed into mma.m16n8k16 B-fragment order
__device__ unsigned short g_whi[2][16384];
__device__ unsigned short g_wlo[2][16384];

// ---------------- helpers ----------------------------------------------------
__device__ __forceinline__ float lrelu(float x) { return x > 0.f ? x : NEG_SLOPE * x; }

__device__ __forceinline__ int2 get_edge(const void* ei, int e, int E) {
    if (g_is64) {
        const long long* p = (const long long*)ei;
        return make_int2((int)p[e], (int)p[E + e]);
    } else {
        const int* p = (const int*)ei;
        return make_int2(p[e], p[E + e]);
    }
}

__device__ __forceinline__ void mma_f16(float* c, uint32_t a0, uint32_t a1,
                                        uint32_t a2, uint32_t a3,
                                        uint32_t b0, uint32_t b1) {
    asm volatile(
        "mma.sync.aligned.m16n8k16.row.col.f32.f16.f16.f32 "
        "{%0,%1,%2,%3}, {%4,%5,%6,%7}, {%8,%9}, {%0,%1,%2,%3};"
        : "+f"(c[0]), "+f"(c[1]), "+f"(c[2]), "+f"(c[3])
        : "r"(a0), "r"(a1), "r"(a2), "r"(a3), "r"(b0), "r"(b1));
}

// ---------------- misc kernels ----------------------------------------------
__global__ void k_detect(const int* __restrict__ p) {
    if (threadIdx.x == 0 && blockIdx.x == 0) {
        int is64 = 1;
        for (int i = 1; i < 128; i += 2)
            if (p[i] != 0) { is64 = 0; break; }
        g_is64 = is64;
    }
}

__global__ void k_hist(const void* __restrict__ ei, int E) {
    const int e = blockIdx.x * 256 + threadIdx.x;
    if (e >= E) return;
    const int2 sd = get_edge(ei, e, E);
    atomicAdd(&g_deg[sd.y], 1);
}

__global__ __launch_bounds__(1024)
void k_blockred(int Nn) {
    const int t = threadIdx.x;
    const int base = blockIdx.x * SCAN_CHUNK + t * 4;
    int s = 0;
#pragma unroll
    for (int i = 0; i < 4; ++i) {
        const int idx = base + i;
        if (idx < Nn) s += g_deg[idx];
    }
#pragma unroll
    for (int off = 16; off; off >>= 1) s += __shfl_xor_sync(0xffffffffu, s, off);
    __shared__ int wsum[32];
    if ((t & 31) == 0) wsum[t >> 5] = s;
    __syncthreads();
    if (t < 32) {
        int v = wsum[t];
#pragma unroll
        for (int off = 16; off; off >>= 1) v += __shfl_xor_sync(0xffffffffu, v, off);
        if (t == 0) g_part[blockIdx.x] = v;
    }
}

__global__ void k_scanpart(int nparts) {
    if (threadIdx.x == 0) {
        int run = 0;
        for (int i = 0; i < nparts; ++i) {
            const int v = g_part[i];
            g_part[i] = run;
            run += v;
        }
        g_rowp[0] = 0;
    }
}

__global__ __launch_bounds__(1024)
void k_blockscan(int Nn) {
    __shared__ int wsum[32];
    const int t = threadIdx.x;
    const int lane = t & 31;
    const int wid  = t >> 5;
    const int base = blockIdx.x * SCAN_CHUNK + t * 4;

    int vals[4];
    int local = 0;
#pragma unroll
    for (int i = 0; i < 4; ++i) {
        const int idx = base + i;
        vals[i] = (idx < Nn) ? g_deg[idx] : 0;
        local += vals[i];
    }
    int x = local;
#pragma unroll
    for (int off = 1; off < 32; off <<= 1) {
        const int n = __shfl_up_sync(0xffffffffu, x, off);
        if (lane >= off) x += n;
    }
    if (lane == 31) wsum[wid] = x;
    __syncthreads();
    if (wid == 0) {
        int v = wsum[lane];
#pragma unroll
        for (int off = 1; off < 32; off <<= 1) {
            const int n = __shfl_up_sync(0xffffffffu, v, off);
            if (lane >= off) v += n;
        }
        wsum[lane] = v;
    }
    __syncthreads();
    const int warpoff = (wid > 0) ? wsum[wid - 1] : 0;
    int run = g_part[blockIdx.x] + warpoff + (x - local);
#pragma unroll
    for (int i = 0; i < 4; ++i) {
        const int idx = base + i;
        if (idx < Nn) {
            g_cursor[idx]   = run;
            g_rowp[idx + 1] = run + vals[i];
        }
        run += vals[i];
    }
}

__global__ void k_scatter(const void* __restrict__ ei, int E) {
    const int e = blockIdx.x * 256 + threadIdx.x;
    if (e >= E) return;
    const int2 sd = get_edge(ei, e, E);
    const int pos = atomicAdd(&g_cursor[sd.y], 1);
    g_csrc[pos] = sd.x;
}

// ---- W prep: fp32 W[k,n] -> fp16 hi/lo in per-lane mma B-fragment order ----
__global__ void k_wprep(const float* __restrict__ W1, const float* __restrict__ W2) {
    const int idx = blockIdx.x * 256 + threadIdx.x;
    if (idx >= 32768) return;
    const int layer = idx >> 14;
    const int e = idx & 16383;
    const int k = e >> 7, n = e & 127;
    const float w = (layer ? W2 : W1)[k * 128 + n];
    __half hi = __float2half_rn(w);
    __half lo = __float2half_rn(w - __half2float(hi));
    const int kk = k >> 4, kin = k & 15;
    const int reg = kin >> 3, t = (kin & 7) >> 1, half = kin & 1;
    const int j = n >> 3, g = n & 7;
    const int lane = g * 4 + t;
    const int off = ((kk * 16 + j) * 32 + lane) * 4 + reg * 2 + half;
    g_whi[layer][off] = *(unsigned short*)&hi;
    g_wlo[layer][off] = *(unsigned short*)&lo;
}

// ---- HMMA GEMM: 128-row tile per block (8 warps x 16 rows), fp16 operands.
// A stored once in fp16; W split hi/lo. D = A*Whi + A*Wlo (fp32 accumulate).
#define SM_A    0
#define SM_W_HI 34816
#define SM_W_LO 67584
#define SMEM_SZ 100352
#define A_STRIDE 272   // bytes per A smem row (136 fp16) - conflict-free

__global__ __launch_bounds__(256, 2)
void k_gemm_mma(const float* __restrict__ A, int layer,
                const float* __restrict__ a_s, const float* __restrict__ a_d,
                __half* __restrict__ hout, float4* __restrict__ asout,
                float4* __restrict__ adout, int Nn) {
    extern __shared__ __align__(16) char smem[];
    const int tid  = threadIdx.x;
    const int lane = tid & 31;
    const int wid  = tid >> 5;
    const int g    = lane >> 2;
    const int t    = lane & 3;
    const int rowBase = blockIdx.x * 128;

    {
        const uint4* shi = (const uint4*)g_whi[layer];
        const uint4* slo = (const uint4*)g_wlo[layer];
        uint4* dhi = (uint4*)(smem + SM_W_HI);
        uint4* dlo = (uint4*)(smem + SM_W_LO);
        for (int i = tid; i < 2048; i += 256) { dhi[i] = shi[i]; dlo[i] = slo[i]; }
    }
    for (int idx = tid; idx < 4096; idx += 256) {
        const int r = idx >> 5;
        const int c4 = (idx & 31) * 4;
        int row = rowBase + r;
        if (row >= Nn) row = Nn - 1;
        const float4 v = *(const float4*)(A + (size_t)row * 128 + c4);
        __half2 p0 = __floats2half2_rn(v.x, v.y);
        __half2 p1 = __floats2half2_rn(v.z, v.w);
        uint2 ph;
        ph.x = *(uint32_t*)&p0;
        ph.y = *(uint32_t*)&p1;
        *(uint2*)(smem + SM_A + r * A_STRIDE + c4 * 2) = ph;
    }
    __syncthreads();

    float acc[16][4];
#pragma unroll
    for (int j = 0; j < 16; ++j)
#pragma unroll
        for (int r = 0; r < 4; ++r) acc[j][r] = 0.f;

    const int abase0 = (wid * 16 + g) * A_STRIDE + t * 4;
#pragma unroll
    for (int kk = 0; kk < 8; ++kk) {
        const int ao = abase0 + kk * 32;
        const uint32_t a0 = *(const uint32_t*)(smem + SM_A + ao);
        const uint32_t a2 = *(const uint32_t*)(smem + SM_A + ao + 16);
        const uint32_t a1 = *(const uint32_t*)(smem + SM_A + ao + 8 * A_STRIDE);
        const uint32_t a3 = *(const uint32_t*)(smem + SM_A + ao + 8 * A_STRIDE + 16);
        const uint2* whrow = (const uint2*)(smem + SM_W_HI) + kk * 512 + lane;
        const uint2* wlrow = (const uint2*)(smem + SM_W_LO) + kk * 512 + lane;
#pragma unroll
        for (int j = 0; j < 16; ++j) {
            const uint2 bh = whrow[j * 32];
            const uint2 bl = wlrow[j * 32];
            mma_f16(acc[j], a0, a1, a2, a3, bh.x, bh.y);
            mma_f16(acc[j], a0, a1, a2, a3, bl.x, bl.y);
        }
    }

    // epilogue: rows r0 = rowBase + wid*16 + g, r1 = r0 + 8; h stored fp16
    const int r0 = rowBase + wid * 16 + g;
    const int r1 = r0 + 8;
    float ps0[4] = {0, 0, 0, 0}, ps1[4] = {0, 0, 0, 0};
    float pd0[4] = {0, 0, 0, 0}, pd1[4] = {0, 0, 0, 0};
#pragma unroll
    for (int j = 0; j < 16; ++j) {
        const int col = j * 8 + t * 2;
        const int h = j >> 2;
        const float s0 = a_s[col], s1 = a_s[col + 1];
        const float d0 = a_d[col], d1 = a_d[col + 1];
        ps0[h] += acc[j][0] * s0 + acc[j][1] * s1;
        pd0[h] += acc[j][0] * d0 + acc[j][1] * d1;
        ps1[h] += acc[j][2] * s0 + acc[j][3] * s1;
        pd1[h] += acc[j][2] * d0 + acc[j][3] * d1;
        if (r0 < Nn) *(__half2*)(hout + (size_t)r0 * 128 + col) = __floats2half2_rn(acc[j][0], acc[j][1]);
        if (r1 < Nn) *(__half2*)(hout + (size_t)r1 * 128 + col) = __floats2half2_rn(acc[j][2], acc[j][3]);
    }
#pragma unroll
    for (int m = 1; m <= 2; m <<= 1) {
#pragma unroll
        for (int h = 0; h < 4; ++h) {
            ps0[h] += __shfl_xor_sync(0xffffffffu, ps0[h], m);
            ps1[h] += __shfl_xor_sync(0xffffffffu, ps1[h], m);
            pd0[h] += __shfl_xor_sync(0xffffffffu, pd0[h], m);
            pd1[h] += __shfl_xor_sync(0xffffffffu, pd1[h], m);
        }
    }
    if (t == 0) {
        if (r0 < Nn) {
            asout[r0] = make_float4(ps0[0], ps0[1], ps0[2], ps0[3]);
            adout[r0] = make_float4(pd0[0], pd0[1], pd0[2], pd0[3]);
        }
        if (r1 < Nn) {
            asout[r1] = make_float4(ps1[0], ps1[1], ps1[2], ps1[3]);
            adout[r1] = make_float4(pd1[0], pd1[1], pd1[2], pd1[3]);
        }
    }
}

// ---- fused GAT aggregation: one warp per dst node, fp16 h gather,
// 2-way software-pipelined inner loop.
__global__ __launch_bounds__(256)
void k_gat_agg(const __half* __restrict__ h, float4* __restrict__ out,
               const float* __restrict__ bias, int Nn) {
    __shared__ float wsm[8][32][4];
    __shared__ int   ssm[8][32];

    const int warp = (blockIdx.x * 256 + threadIdx.x) >> 5;
    const int lane = threadIdx.x & 31;
    const int w    = threadIdx.x >> 5;
    if (warp >= Nn) return;
    const int v = warp;
    const int head = lane >> 3;

    const float4 adv = g_ad[v];

    float4 acc;
    float  den;
    {
        const float4 asv = g_as[v];
        float4 we;
        we.x = __expf(lrelu(asv.x + adv.x));
        we.y = __expf(lrelu(asv.y + adv.y));
        we.z = __expf(lrelu(asv.z + adv.z));
        we.w = __expf(lrelu(asv.w + adv.w));
        const float wh = (head == 0) ? we.x : (head == 1) ? we.y : (head == 2) ? we.z : we.w;
        const uint2 hv = ((const uint2*)(h + (size_t)v * 128))[lane];
        const float2 p0 = __half22float2(*(const __half2*)&hv.x);
        const float2 p1 = __half22float2(*(const __half2*)&hv.y);
        acc = make_float4(p0.x * wh, p0.y * wh, p1.x * wh, p1.y * wh);
        den = wh;
    }

    const int beg = g_rowp[v];
    const int end = g_rowp[v + 1];
    for (int base = beg; base < end; base += 32) {
        int n = end - base; if (n > 32) n = 32;
        int sidx = 0;
        float4 we = make_float4(0.f, 0.f, 0.f, 0.f);
        if (lane < n) {
            sidx = g_csrc[base + lane];
            const float4 s = g_as[sidx];
            we.x = __expf(lrelu(s.x + adv.x));
            we.y = __expf(lrelu(s.y + adv.y));
            we.z = __expf(lrelu(s.z + adv.z));
            we.w = __expf(lrelu(s.w + adv.w));
        }
        ssm[w][lane] = sidx;
        *(float4*)&wsm[w][lane][0] = we;
        __syncwarp();

        int j = 0;
        if (n & 1) {
            const int   sj = ssm[w][0];
            const float wj = wsm[w][0][head];
            const uint2 hv = ((const uint2*)(h + (size_t)sj * 128))[lane];
            const float2 p0 = __half22float2(*(const __half2*)&hv.x);
            const float2 p1 = __half22float2(*(const __half2*)&hv.y);
            acc.x += wj * p0.x; acc.y += wj * p0.y;
            acc.z += wj * p1.x; acc.w += wj * p1.y;
            den += wj;
            j = 1;
        }
        for (; j < n; j += 2) {
            const int   s0 = ssm[w][j];
            const int   s1 = ssm[w][j + 1];
            const uint2 h0 = ((const uint2*)(h + (size_t)s0 * 128))[lane];
            const uint2 h1 = ((const uint2*)(h + (size_t)s1 * 128))[lane];
            const float w0 = wsm[w][j][head];
            const float w1 = wsm[w][j + 1][head];
            const float2 a0 = __half22float2(*(const __half2*)&h0.x);
            const float2 a1 = __half22float2(*(const __half2*)&h0.y);
            const float2 b0 = __half22float2(*(const __half2*)&h1.x);
            const float2 b1 = __half22float2(*(const __half2*)&h1.y);
            acc.x += w0 * a0.x + w1 * b0.x;
            acc.y += w0 * a0.y + w1 * b0.y;
            acc.z += w0 * a1.x + w1 * b1.x;
            acc.w += w0 * a1.y + w1 * b1.y;
            den   += w0 + w1;
        }
        __syncwarp();
    }

    const float inv = __fdividef(1.f, den);
    const float4 b4 = ((const float4*)bias)[lane];
    float4 o;
    o.x = fmaxf(acc.x * inv + b4.x, 0.f);
    o.y = fmaxf(acc.y * inv + b4.y, 0.f);
    o.z = fmaxf(acc.z * inv + b4.z, 0.f);
    o.w = fmaxf(acc.w * inv + b4.w, 0.f);
    out[(size_t)v * 32 + lane] = o;
}

// ---------------- launch -----------------------------------------------------
extern "C" void kernel_launch(void* const* d_in, const int* in_sizes, int n_in,
                              void* d_out, int out_size) {
    const float* x   = (const float*)d_in[0];
    const void*  ei  = d_in[1];
    const float* W1  = (const float*)d_in[2];
    const float* as1 = (const float*)d_in[3];
    const float* ad1 = (const float*)d_in[4];
    const float* b1  = (const float*)d_in[5];
    const float* W2  = (const float*)d_in[6];
    const float* as2 = (const float*)d_in[7];
    const float* ad2 = (const float*)d_in[8];
    const float* b2  = (const float*)d_in[9];

    const int N  = in_sizes[0] / 128;
    const int E  = in_sizes[1] / 2;

    void* ph = nullptr;   cudaGetSymbolAddress(&ph,  g_hh);
    void* po = nullptr;   cudaGetSymbolAddress(&po,  g_out);
    void* pas = nullptr;  cudaGetSymbolAddress(&pas, g_as);
    void* pad = nullptr;  cudaGetSymbolAddress(&pad, g_ad);
    void* pdeg = nullptr; cudaGetSymbolAddress(&pdeg, g_deg);

    const int ebl = (E + 255) / 256;
    const int abl = (N * 32 + 255) / 256;
    const int gbl = (N + 127) / 128;
    const int sbl = (N + SCAN_CHUNK - 1) / SCAN_CHUNK;

    cudaFuncSetAttribute(k_gemm_mma, cudaFuncAttributeMaxDynamicSharedMemorySize, SMEM_SZ);

    static cudaStream_t s2 = nullptr;
    static cudaEvent_t evFork = nullptr, evJoin = nullptr;
    if (!s2) {
        cudaStreamCreateWithFlags(&s2, cudaStreamNonBlocking);
        cudaEventCreateWithFlags(&evFork, cudaEventDisableTiming);
        cudaEventCreateWithFlags(&evJoin, cudaEventDisableTiming);
    }

    k_detect<<<1, 32>>>((const int*)ei);

    // ---- fork: CSR build on s2, concurrent with W prep + layer-1 GEMM ----
    cudaEventRecord(evFork, 0);
    cudaStreamWaitEvent(s2, evFork, 0);

    cudaMemsetAsync(pdeg, 0, N * sizeof(int), s2);
    k_hist<<<ebl, 256, 0, s2>>>(ei, E);
    k_blockred<<<sbl, 1024, 0, s2>>>(N);
    k_scanpart<<<1, 32, 0, s2>>>(sbl);
    k_blockscan<<<sbl, 1024, 0, s2>>>(N);
    k_scatter<<<ebl, 256, 0, s2>>>(ei, E);
    cudaEventRecord(evJoin, s2);

    // ---- main stream: layer-1 GEMM ----
    k_wprep<<<128, 256>>>(W1, W2);
    k_gemm_mma<<<gbl, 256, SMEM_SZ>>>(x, 0, as1, ad1, (__half*)ph,
                                      (float4*)pas, (float4*)pad, N);

    // ---- join: aggregation needs both CSR and GEMM-1 ----
    cudaStreamWaitEvent(0, evJoin, 0);
    k_gat_agg<<<abl, 256>>>((const __half*)ph, (float4*)po, b1, N);

    // ---- layer 2 ----
    k_gemm_mma<<<gbl, 256, SMEM_SZ>>>((const float*)po, 1, as2, ad2, (__half*)ph,
                                      (float4*)pas, (float4*)pad, N);
    k_gat_agg<<<abl, 256>>>((const __half*)ph, (float4*)d_out, b2, N);
}

// round 9
// speedup vs baseline: 4.1136x; 1.1481x over previous
#include <cuda_runtime.h>
#include <cuda_bf16.h>
#include <cuda_fp16.h>
#include <cstdint>

// Problem shape: N=100000 nodes, E=1600000 edges, D = H*C = 128, H=4, C=32.
#define N_MAX  100000
#define E_MAX  1600000
#define NEG_SLOPE 0.2f
#define SCAN_CHUNK 4096

// ---------------- scratch (device globals) ----------------------------------
__device__ int    g_is64;
__device__ __half g_hh[N_MAX * 128];      // h = x@W in fp16 (gather payload)
__device__ float4 g_as[N_MAX];            // alpha_src per node [N,4]
__device__ float4 g_ad[N_MAX];            // alpha_dst per node [N,4]
__device__ float4 g_out[N_MAX * 32];      // layer-1 output (fp32)
__device__ int    g_deg[N_MAX];
__device__ int    g_rowp[N_MAX + 1];
__device__ int    g_cursor[N_MAX];
__device__ int    g_csrc[E_MAX];
__device__ int    g_part[64];
// W in fp16, pre-packed into mma.m16n8k16 B-fragment order
__device__ unsigned short g_w[2][16384];

// ---------------- helpers ----------------------------------------------------
__device__ __forceinline__ float lrelu(float x) { return x > 0.f ? x : NEG_SLOPE * x; }

__device__ __forceinline__ int2 get_edge(const void* ei, int e, int E) {
    if (g_is64) {
        const long long* p = (const long long*)ei;
        return make_int2((int)p[e], (int)p[E + e]);
    } else {
        const int* p = (const int*)ei;
        return make_int2(p[e], p[E + e]);
    }
}

__device__ __forceinline__ void mma_f16(float* c, uint32_t a0, uint32_t a1,
                                        uint32_t a2, uint32_t a3,
                                        uint32_t b0, uint32_t b1) {
    asm volatile(
        "mma.sync.aligned.m16n8k16.row.col.f32.f16.f16.f32 "
        "{%0,%1,%2,%3}, {%4,%5,%6,%7}, {%8,%9}, {%0,%1,%2,%3};"
        : "+f"(c[0]), "+f"(c[1]), "+f"(c[2]), "+f"(c[3])
        : "r"(a0), "r"(a1), "r"(a2), "r"(a3), "r"(b0), "r"(b1));
}

// ---------------- misc kernels ----------------------------------------------
__global__ void k_detect(const int* __restrict__ p) {
    if (threadIdx.x == 0 && blockIdx.x == 0) {
        int is64 = 1;
        for (int i = 1; i < 128; i += 2)
            if (p[i] != 0) { is64 = 0; break; }
        g_is64 = is64;
    }
}

__global__ void k_hist(const void* __restrict__ ei, int E) {
    const int e = blockIdx.x * 256 + threadIdx.x;
    if (e >= E) return;
    const int2 sd = get_edge(ei, e, E);
    atomicAdd(&g_deg[sd.y], 1);
}

__global__ __launch_bounds__(1024)
void k_blockred(int Nn) {
    const int t = threadIdx.x;
    const int base = blockIdx.x * SCAN_CHUNK + t * 4;
    int s = 0;
#pragma unroll
    for (int i = 0; i < 4; ++i) {
        const int idx = base + i;
        if (idx < Nn) s += g_deg[idx];
    }
#pragma unroll
    for (int off = 16; off; off >>= 1) s += __shfl_xor_sync(0xffffffffu, s, off);
    __shared__ int wsum[32];
    if ((t & 31) == 0) wsum[t >> 5] = s;
    __syncthreads();
    if (t < 32) {
        int v = wsum[t];
#pragma unroll
        for (int off = 16; off; off >>= 1) v += __shfl_xor_sync(0xffffffffu, v, off);
        if (t == 0) g_part[blockIdx.x] = v;
    }
}

// warp-parallel exclusive scan of block partials (nparts <= 32)
__global__ void k_scanpart(int nparts) {
    const int lane = threadIdx.x;
    int v = (lane < nparts) ? g_part[lane] : 0;
    int x = v;
#pragma unroll
    for (int off = 1; off < 32; off <<= 1) {
        const int n = __shfl_up_sync(0xffffffffu, x, off);
        if (lane >= off) x += n;
    }
    if (lane < nparts) g_part[lane] = x - v;   // exclusive
    if (lane == 0) g_rowp[0] = 0;
}

__global__ __launch_bounds__(1024)
void k_blockscan(int Nn) {
    __shared__ int wsum[32];
    const int t = threadIdx.x;
    const int lane = t & 31;
    const int wid  = t >> 5;
    const int base = blockIdx.x * SCAN_CHUNK + t * 4;

    int vals[4];
    int local = 0;
#pragma unroll
    for (int i = 0; i < 4; ++i) {
        const int idx = base + i;
        vals[i] = (idx < Nn) ? g_deg[idx] : 0;
        local += vals[i];
    }
    int x = local;
#pragma unroll
    for (int off = 1; off < 32; off <<= 1) {
        const int n = __shfl_up_sync(0xffffffffu, x, off);
        if (lane >= off) x += n;
    }
    if (lane == 31) wsum[wid] = x;
    __syncthreads();
    if (wid == 0) {
        int v = wsum[lane];
#pragma unroll
        for (int off = 1; off < 32; off <<= 1) {
            const int n = __shfl_up_sync(0xffffffffu, v, off);
            if (lane >= off) v += n;
        }
        wsum[lane] = v;
    }
    __syncthreads();
    const int warpoff = (wid > 0) ? wsum[wid - 1] : 0;
    int run = g_part[blockIdx.x] + warpoff + (x - local);
#pragma unroll
    for (int i = 0; i < 4; ++i) {
        const int idx = base + i;
        if (idx < Nn) {
            g_cursor[idx]   = run;
            g_rowp[idx + 1] = run + vals[i];
        }
        run += vals[i];
    }
}

__global__ void k_scatter(const void* __restrict__ ei, int E) {
    const int e = blockIdx.x * 256 + threadIdx.x;
    if (e >= E) return;
    const int2 sd = get_edge(ei, e, E);
    const int pos = atomicAdd(&g_cursor[sd.y], 1);
    g_csrc[pos] = sd.x;
}

// ---- W prep: fp32 W[k,n] -> fp16 in per-lane mma B-fragment order ----------
__global__ void k_wprep(const float* __restrict__ W1, const float* __restrict__ W2) {
    const int idx = blockIdx.x * 256 + threadIdx.x;
    if (idx >= 32768) return;
    const int layer = idx >> 14;
    const int e = idx & 16383;
    const int k = e >> 7, n = e & 127;
    const float w = (layer ? W2 : W1)[k * 128 + n];
    __half hi = __float2half_rn(w);
    const int kk = k >> 4, kin = k & 15;
    const int reg = kin >> 3, t = (kin & 7) >> 1, half = kin & 1;
    const int j = n >> 3, g = n & 7;
    const int lane = g * 4 + t;
    const int off = ((kk * 16 + j) * 32 + lane) * 4 + reg * 2 + half;
    g_w[layer][off] = *(unsigned short*)&hi;
}

// ---- HMMA GEMM: 128-row tile per block (8 warps x 16 rows), fp16 operands.
#define SM_A  0
#define SM_W  34816
#define SMEM_SZ 67584
#define A_STRIDE 272   // bytes per A smem row (136 fp16) - conflict-free

__global__ __launch_bounds__(256, 2)
void k_gemm_mma(const float* __restrict__ A, int layer,
                const float* __restrict__ a_s, const float* __restrict__ a_d,
                __half* __restrict__ hout, float4* __restrict__ asout,
                float4* __restrict__ adout, int Nn) {
    extern __shared__ __align__(16) char smem[];
    const int tid  = threadIdx.x;
    const int lane = tid & 31;
    const int wid  = tid >> 5;
    const int g    = lane >> 2;
    const int t    = lane & 3;
    const int rowBase = blockIdx.x * 128;

    {
        const uint4* sw = (const uint4*)g_w[layer];
        uint4* dw = (uint4*)(smem + SM_W);
        for (int i = tid; i < 2048; i += 256) dw[i] = sw[i];
    }
    for (int idx = tid; idx < 4096; idx += 256) {
        const int r = idx >> 5;
        const int c4 = (idx & 31) * 4;
        int row = rowBase + r;
        if (row >= Nn) row = Nn - 1;
        const float4 v = *(const float4*)(A + (size_t)row * 128 + c4);
        __half2 p0 = __floats2half2_rn(v.x, v.y);
        __half2 p1 = __floats2half2_rn(v.z, v.w);
        uint2 ph;
        ph.x = *(uint32_t*)&p0;
        ph.y = *(uint32_t*)&p1;
        *(uint2*)(smem + SM_A + r * A_STRIDE + c4 * 2) = ph;
    }
    __syncthreads();

    float acc[16][4];
#pragma unroll
    for (int j = 0; j < 16; ++j)
#pragma unroll
        for (int r = 0; r < 4; ++r) acc[j][r] = 0.f;

    const int abase0 = (wid * 16 + g) * A_STRIDE + t * 4;
#pragma unroll
    for (int kk = 0; kk < 8; ++kk) {
        const int ao = abase0 + kk * 32;
        const uint32_t a0 = *(const uint32_t*)(smem + SM_A + ao);
        const uint32_t a2 = *(const uint32_t*)(smem + SM_A + ao + 16);
        const uint32_t a1 = *(const uint32_t*)(smem + SM_A + ao + 8 * A_STRIDE);
        const uint32_t a3 = *(const uint32_t*)(smem + SM_A + ao + 8 * A_STRIDE + 16);
        const uint2* wrow = (const uint2*)(smem + SM_W) + kk * 512 + lane;
#pragma unroll
        for (int j = 0; j < 16; ++j) {
            const uint2 b = wrow[j * 32];
            mma_f16(acc[j], a0, a1, a2, a3, b.x, b.y);
        }
    }

    // epilogue: rows r0 = rowBase + wid*16 + g, r1 = r0 + 8; h stored fp16
    const int r0 = rowBase + wid * 16 + g;
    const int r1 = r0 + 8;
    float ps0[4] = {0, 0, 0, 0}, ps1[4] = {0, 0, 0, 0};
    float pd0[4] = {0, 0, 0, 0}, pd1[4] = {0, 0, 0, 0};
#pragma unroll
    for (int j = 0; j < 16; ++j) {
        const int col = j * 8 + t * 2;
        const int h = j >> 2;
        const float s0 = a_s[col], s1 = a_s[col + 1];
        const float d0 = a_d[col], d1 = a_d[col + 1];
        ps0[h] += acc[j][0] * s0 + acc[j][1] * s1;
        pd0[h] += acc[j][0] * d0 + acc[j][1] * d1;
        ps1[h] += acc[j][2] * s0 + acc[j][3] * s1;
        pd1[h] += acc[j][2] * d0 + acc[j][3] * d1;
        if (r0 < Nn) *(__half2*)(hout + (size_t)r0 * 128 + col) = __floats2half2_rn(acc[j][0], acc[j][1]);
        if (r1 < Nn) *(__half2*)(hout + (size_t)r1 * 128 + col) = __floats2half2_rn(acc[j][2], acc[j][3]);
    }
#pragma unroll
    for (int m = 1; m <= 2; m <<= 1) {
#pragma unroll
        for (int h = 0; h < 4; ++h) {
            ps0[h] += __shfl_xor_sync(0xffffffffu, ps0[h], m);
            ps1[h] += __shfl_xor_sync(0xffffffffu, ps1[h], m);
            pd0[h] += __shfl_xor_sync(0xffffffffu, pd0[h], m);
            pd1[h] += __shfl_xor_sync(0xffffffffu, pd1[h], m);
        }
    }
    if (t == 0) {
        if (r0 < Nn) {
            asout[r0] = make_float4(ps0[0], ps0[1], ps0[2], ps0[3]);
            adout[r0] = make_float4(pd0[0], pd0[1], pd0[2], pd0[3]);
        }
        if (r1 < Nn) {
            asout[r1] = make_float4(ps1[0], ps1[1], ps1[2], ps1[3]);
            adout[r1] = make_float4(pd1[0], pd1[1], pd1[2], pd1[3]);
        }
    }
}

// ---- fused GAT aggregation: one warp per dst node, fp16 h gather,
// 4-way software-pipelined inner loop.
__global__ __launch_bounds__(256)
void k_gat_agg(const __half* __restrict__ h, float4* __restrict__ out,
               const float* __restrict__ bias, int Nn) {
    __shared__ float wsm[8][32][4];
    __shared__ int   ssm[8][32];

    const int warp = (blockIdx.x * 256 + threadIdx.x) >> 5;
    const int lane = threadIdx.x & 31;
    const int w    = threadIdx.x >> 5;
    if (warp >= Nn) return;
    const int v = warp;
    const int head = lane >> 3;

    const float4 adv = g_ad[v];

    float4 acc;
    float  den;
    {
        const float4 asv = g_as[v];
        float4 we;
        we.x = __expf(lrelu(asv.x + adv.x));
        we.y = __expf(lrelu(asv.y + adv.y));
        we.z = __expf(lrelu(asv.z + adv.z));
        we.w = __expf(lrelu(asv.w + adv.w));
        const float wh = (head == 0) ? we.x : (head == 1) ? we.y : (head == 2) ? we.z : we.w;
        const uint2 hv = ((const uint2*)(h + (size_t)v * 128))[lane];
        const float2 p0 = __half22float2(*(const __half2*)&hv.x);
        const float2 p1 = __half22float2(*(const __half2*)&hv.y);
        acc = make_float4(p0.x * wh, p0.y * wh, p1.x * wh, p1.y * wh);
        den = wh;
    }

    const int beg = g_rowp[v];
    const int end = g_rowp[v + 1];
    for (int base = beg; base < end; base += 32) {
        int n = end - base; if (n > 32) n = 32;
        int sidx = 0;
        float4 we = make_float4(0.f, 0.f, 0.f, 0.f);
        if (lane < n) {
            sidx = g_csrc[base + lane];
            const float4 s = g_as[sidx];
            we.x = __expf(lrelu(s.x + adv.x));
            we.y = __expf(lrelu(s.y + adv.y));
            we.z = __expf(lrelu(s.z + adv.z));
            we.w = __expf(lrelu(s.w + adv.w));
        }
        ssm[w][lane] = sidx;
        *(float4*)&wsm[w][lane][0] = we;
        __syncwarp();

        int j = 0;
        for (; j + 4 <= n; j += 4) {
            const int   s0 = ssm[w][j],     s1 = ssm[w][j + 1];
            const int   s2 = ssm[w][j + 2], s3 = ssm[w][j + 3];
            const uint2 h0 = ((const uint2*)(h + (size_t)s0 * 128))[lane];
            const uint2 h1 = ((const uint2*)(h + (size_t)s1 * 128))[lane];
            const uint2 h2 = ((const uint2*)(h + (size_t)s2 * 128))[lane];
            const uint2 h3 = ((const uint2*)(h + (size_t)s3 * 128))[lane];
            const float w0 = wsm[w][j][head],     w1 = wsm[w][j + 1][head];
            const float w2 = wsm[w][j + 2][head], w3 = wsm[w][j + 3][head];
            float2 p;
            p = __half22float2(*(const __half2*)&h0.x); acc.x += w0 * p.x; acc.y += w0 * p.y;
            p = __half22float2(*(const __half2*)&h0.y); acc.z += w0 * p.x; acc.w += w0 * p.y;
            p = __half22float2(*(const __half2*)&h1.x); acc.x += w1 * p.x; acc.y += w1 * p.y;
            p = __half22float2(*(const __half2*)&h1.y); acc.z += w1 * p.x; acc.w += w1 * p.y;
            p = __half22float2(*(const __half2*)&h2.x); acc.x += w2 * p.x; acc.y += w2 * p.y;
            p = __half22float2(*(const __half2*)&h2.y); acc.z += w2 * p.x; acc.w += w2 * p.y;
            p = __half22float2(*(const __half2*)&h3.x); acc.x += w3 * p.x; acc.y += w3 * p.y;
            p = __half22float2(*(const __half2*)&h3.y); acc.z += w3 * p.x; acc.w += w3 * p.y;
            den += w0 + w1 + w2 + w3;
        }
        for (; j < n; ++j) {
            const int   sj = ssm[w][j];
            const float wj = wsm[w][j][head];
            const uint2 hv = ((const uint2*)(h + (size_t)sj * 128))[lane];
            const float2 p0 = __half22float2(*(const __half2*)&hv.x);
            const float2 p1 = __half22float2(*(const __half2*)&hv.y);
            acc.x += wj * p0.x; acc.y += wj * p0.y;
            acc.z += wj * p1.x; acc.w += wj * p1.y;
            den += wj;
        }
        __syncwarp();
    }

    const float inv = __fdividef(1.f, den);
    const float4 b4 = ((const float4*)bias)[lane];
    float4 o;
    o.x = fmaxf(acc.x * inv + b4.x, 0.f);
    o.y = fmaxf(acc.y * inv + b4.y, 0.f);
    o.z = fmaxf(acc.z * inv + b4.z, 0.f);
    o.w = fmaxf(acc.w * inv + b4.w, 0.f);
    out[(size_t)v * 32 + lane] = o;
}

// ---------------- launch -----------------------------------------------------
extern "C" void kernel_launch(void* const* d_in, const int* in_sizes, int n_in,
                              void* d_out, int out_size) {
    const float* x   = (const float*)d_in[0];
    const void*  ei  = d_in[1];
    const float* W1  = (const float*)d_in[2];
    const float* as1 = (const float*)d_in[3];
    const float* ad1 = (const float*)d_in[4];
    const float* b1  = (const float*)d_in[5];
    const float* W2  = (const float*)d_in[6];
    const float* as2 = (const float*)d_in[7];
    const float* ad2 = (const float*)d_in[8];
    const float* b2  = (const float*)d_in[9];

    const int N  = in_sizes[0] / 128;
    const int E  = in_sizes[1] / 2;

    void* ph = nullptr;   cudaGetSymbolAddress(&ph,  g_hh);
    void* po = nullptr;   cudaGetSymbolAddress(&po,  g_out);
    void* pas = nullptr;  cudaGetSymbolAddress(&pas, g_as);
    void* pad = nullptr;  cudaGetSymbolAddress(&pad, g_ad);
    void* pdeg = nullptr; cudaGetSymbolAddress(&pdeg, g_deg);

    const int ebl = (E + 255) / 256;
    const int abl = (N * 32 + 255) / 256;
    const int gbl = (N + 127) / 128;
    const int sbl = (N + SCAN_CHUNK - 1) / SCAN_CHUNK;

    cudaFuncSetAttribute(k_gemm_mma, cudaFuncAttributeMaxDynamicSharedMemorySize, SMEM_SZ);

    static cudaStream_t s2 = nullptr;
    static cudaEvent_t evFork = nullptr, evJoin = nullptr;
    if (!s2) {
        cudaStreamCreateWithFlags(&s2, cudaStreamNonBlocking);
        cudaEventCreateWithFlags(&evFork, cudaEventDisableTiming);
        cudaEventCreateWithFlags(&evJoin, cudaEventDisableTiming);
    }

    k_detect<<<1, 32>>>((const int*)ei);

    // ---- fork: CSR build on s2, concurrent with W prep + layer-1 GEMM ----
    cudaEventRecord(evFork, 0);
    cudaStreamWaitEvent(s2, evFork, 0);

    cudaMemsetAsync(pdeg, 0, N * sizeof(int), s2);
    k_hist<<<ebl, 256, 0, s2>>>(ei, E);
    k_blockred<<<sbl, 1024, 0, s2>>>(N);
    k_scanpart<<<1, 32, 0, s2>>>(sbl);
    k_blockscan<<<sbl, 1024, 0, s2>>>(N);
    k_scatter<<<ebl, 256, 0, s2>>>(ei, E);
    cudaEventRecord(evJoin, s2);

    // ---- main stream: layer-1 GEMM ----
    k_wprep<<<128, 256>>>(W1, W2);
    k_gemm_mma<<<gbl, 256, SMEM_SZ>>>(x, 0, as1, ad1, (__half*)ph,
                                      (float4*)pas, (float4*)pad, N);

    // ---- join: aggregation needs both CSR and GEMM-1 ----
    cudaStreamWaitEvent(0, evJoin, 0);
    k_gat_agg<<<abl, 256>>>((const __half*)ph, (float4*)po, b1, N);

    // ---- layer 2 ----
    k_gemm_mma<<<gbl, 256, SMEM_SZ>>>((const float*)po, 1, as2, ad2, (__half*)ph,
                                      (float4*)pas, (float4*)pad, N);
    k_gat_agg<<<abl, 256>>>((const __half*)ph, (float4*)d_out, b2, N);
}

// round 10
// speedup vs baseline: 4.3256x; 1.0515x over previous
#include <cuda_runtime.h>
#include <cuda_bf16.h>
#include <cuda_fp16.h>
#include <cstdint>

// Problem shape: N=100000 nodes, E=1600000 edges, D = H*C = 128, H=4, C=32.
#define N_MAX  100000
#define E_MAX  1600000
#define NEG_SLOPE 0.2f
#define SCAN_CHUNK 4096

// ---------------- scratch (device globals) ----------------------------------
__device__ int    g_is64;
__device__ __half g_hh[N_MAX * 128];      // h = x@W in fp16 (gather payload)
__device__ __half g_o16[N_MAX * 128];     // layer-1 output in fp16 (GEMM-2 input)
__device__ float4 g_as[N_MAX];            // alpha_src per node [N,4]
__device__ float4 g_ad[N_MAX];            // alpha_dst per node [N,4]
__device__ int    g_deg[N_MAX];
__device__ int    g_rowp[N_MAX + 1];
__device__ int    g_cursor[N_MAX];
__device__ int    g_csrc[E_MAX];
__device__ int    g_part[64];             // scan partial sums
__device__ int    g_poff[64];             // scan exclusive offsets
__device__ int    g_scancnt;
__device__ int    g_scanflag;
// W in fp16, pre-packed into mma.m16n8k16 B-fragment order
__device__ unsigned short g_w[2][16384];

// ---------------- helpers ----------------------------------------------------
__device__ __forceinline__ float lrelu(float x) { return x > 0.f ? x : NEG_SLOPE * x; }

__device__ __forceinline__ int2 get_edge(const void* ei, int e, int E) {
    if (g_is64) {
        const long long* p = (const long long*)ei;
        return make_int2((int)p[e], (int)p[E + e]);
    } else {
        const int* p = (const int*)ei;
        return make_int2(p[e], p[E + e]);
    }
}

__device__ __forceinline__ void mma_f16(float* c, uint32_t a0, uint32_t a1,
                                        uint32_t a2, uint32_t a3,
                                        uint32_t b0, uint32_t b1) {
    asm volatile(
        "mma.sync.aligned.m16n8k16.row.col.f32.f16.f16.f32 "
        "{%0,%1,%2,%3}, {%4,%5,%6,%7}, {%8,%9}, {%0,%1,%2,%3};"
        : "+f"(c[0]), "+f"(c[1]), "+f"(c[2]), "+f"(c[3])
        : "r"(a0), "r"(a1), "r"(a2), "r"(a3), "r"(b0), "r"(b1));
}

// ---------------- misc kernels ----------------------------------------------
// detect dtype + reset scan sync state (runs on s2 before hist/scan)
__global__ void k_detect(const int* __restrict__ p) {
    if (threadIdx.x == 0 && blockIdx.x == 0) {
        int is64 = 1;
        for (int i = 1; i < 128; i += 2)
            if (p[i] != 0) { is64 = 0; break; }
        g_is64 = is64;
        g_scancnt = 0;
        g_scanflag = 0;
    }
}

__global__ void k_hist(const void* __restrict__ ei, int E) {
    const int e = blockIdx.x * 256 + threadIdx.x;
    if (e >= E) return;
    const int2 sd = get_edge(ei, e, E);
    atomicAdd(&g_deg[sd.y], 1);
}

// fused 3-phase scan: per-block reduce -> block0 scans partials -> block scan.
// All nparts (<=64) blocks are resident concurrently (25 blocks of 1024 thr).
__global__ __launch_bounds__(1024)
void k_scan_fused(int Nn, int nparts) {
    __shared__ int wsum[32];
    const int t = threadIdx.x;
    const int lane = t & 31;
    const int wid  = t >> 5;
    const int bid  = blockIdx.x;
    const int base = bid * SCAN_CHUNK + t * 4;

    int vals[4];
    int local = 0;
#pragma unroll
    for (int i = 0; i < 4; ++i) {
        const int idx = base + i;
        vals[i] = (idx < Nn) ? g_deg[idx] : 0;
        local += vals[i];
    }
    int x = local;
#pragma unroll
    for (int off = 1; off < 32; off <<= 1) {
        const int n = __shfl_up_sync(0xffffffffu, x, off);
        if (lane >= off) x += n;
    }
    if (lane == 31) wsum[wid] = x;
    __syncthreads();
    if (wid == 0) {
        int v = wsum[lane];
#pragma unroll
        for (int off = 1; off < 32; off <<= 1) {
            const int n = __shfl_up_sync(0xffffffffu, v, off);
            if (lane >= off) v += n;
        }
        wsum[lane] = v;
    }
    __syncthreads();
    const int warpoff = (wid > 0) ? wsum[wid - 1] : 0;
    const int blocktotal = wsum[31];

    // publish partial, grid-sync via atomic counter + flag
    if (t == 0) {
        g_part[bid] = blocktotal;
        __threadfence();
        atomicAdd(&g_scancnt, 1);
        if (bid == 0) {
            while (*(volatile int*)&g_scancnt < nparts) { }
            int run = 0;
            for (int i = 0; i < nparts; ++i) {
                g_poff[i] = run;
                run += g_part[i];
            }
            g_rowp[0] = 0;
            __threadfence();
            *(volatile int*)&g_scanflag = 1;
        } else {
            while (*(volatile int*)&g_scanflag == 0) { }
        }
    }
    __syncthreads();

    int run = g_poff[bid] + warpoff + (x - local);
#pragma unroll
    for (int i = 0; i < 4; ++i) {
        const int idx = base + i;
        if (idx < Nn) {
            g_cursor[idx]   = run;
            g_rowp[idx + 1] = run + vals[i];
        }
        run += vals[i];
    }
}

__global__ void k_scatter(const void* __restrict__ ei, int E) {
    const int e = blockIdx.x * 256 + threadIdx.x;
    if (e >= E) return;
    const int2 sd = get_edge(ei, e, E);
    const int pos = atomicAdd(&g_cursor[sd.y], 1);
    g_csrc[pos] = sd.x;
}

// ---- W prep: fp32 W[k,n] -> fp16 in per-lane mma B-fragment order ----------
__global__ void k_wprep(const float* __restrict__ W1, const float* __restrict__ W2) {
    const int idx = blockIdx.x * 256 + threadIdx.x;
    if (idx >= 32768) return;
    const int layer = idx >> 14;
    const int e = idx & 16383;
    const int k = e >> 7, n = e & 127;
    const float w = (layer ? W2 : W1)[k * 128 + n];
    __half hi = __float2half_rn(w);
    const int kk = k >> 4, kin = k & 15;
    const int reg = kin >> 3, t = (kin & 7) >> 1, half = kin & 1;
    const int j = n >> 3, g = n & 7;
    const int lane = g * 4 + t;
    const int off = ((kk * 16 + j) * 32 + lane) * 4 + reg * 2 + half;
    g_w[layer][off] = *(unsigned short*)&hi;
}

// ---- HMMA GEMM: 128-row tile per block (8 warps x 16 rows), fp16 operands.
// Input either fp32 (A32) or fp16 (A16, pre-rounded - identical numerics).
#define SM_A  0
#define SM_W  34816
#define SMEM_SZ 67584
#define A_STRIDE 272   // bytes per A smem row (136 fp16) - conflict-free

__global__ __launch_bounds__(256, 2)
void k_gemm_mma(const float* __restrict__ A32, const __half* __restrict__ A16,
                int layer,
                const float* __restrict__ a_s, const float* __restrict__ a_d,
                __half* __restrict__ hout, float4* __restrict__ asout,
                float4* __restrict__ adout, int Nn) {
    extern __shared__ __align__(16) char smem[];
    const int tid  = threadIdx.x;
    const int lane = tid & 31;
    const int wid  = tid >> 5;
    const int g    = lane >> 2;
    const int t    = lane & 3;
    const int rowBase = blockIdx.x * 128;

    {
        const uint4* sw = (const uint4*)g_w[layer];
        uint4* dw = (uint4*)(smem + SM_W);
        for (int i = tid; i < 2048; i += 256) dw[i] = sw[i];
    }
    if (A16) {
        for (int idx = tid; idx < 4096; idx += 256) {
            const int r = idx >> 5;
            const int c4 = (idx & 31) * 4;
            int row = rowBase + r;
            if (row >= Nn) row = Nn - 1;
            const uint2 v = *(const uint2*)(A16 + (size_t)row * 128 + c4);
            *(uint2*)(smem + SM_A + r * A_STRIDE + c4 * 2) = v;
        }
    } else {
        for (int idx = tid; idx < 4096; idx += 256) {
            const int r = idx >> 5;
            const int c4 = (idx & 31) * 4;
            int row = rowBase + r;
            if (row >= Nn) row = Nn - 1;
            const float4 v = *(const float4*)(A32 + (size_t)row * 128 + c4);
            __half2 p0 = __floats2half2_rn(v.x, v.y);
            __half2 p1 = __floats2half2_rn(v.z, v.w);
            uint2 ph;
            ph.x = *(uint32_t*)&p0;
            ph.y = *(uint32_t*)&p1;
            *(uint2*)(smem + SM_A + r * A_STRIDE + c4 * 2) = ph;
        }
    }
    __syncthreads();

    float acc[16][4];
#pragma unroll
    for (int j = 0; j < 16; ++j)
#pragma unroll
        for (int r = 0; r < 4; ++r) acc[j][r] = 0.f;

    const int abase0 = (wid * 16 + g) * A_STRIDE + t * 4;
#pragma unroll
    for (int kk = 0; kk < 8; ++kk) {
        const int ao = abase0 + kk * 32;
        const uint32_t a0 = *(const uint32_t*)(smem + SM_A + ao);
        const uint32_t a2 = *(const uint32_t*)(smem + SM_A + ao + 16);
        const uint32_t a1 = *(const uint32_t*)(smem + SM_A + ao + 8 * A_STRIDE);
        const uint32_t a3 = *(const uint32_t*)(smem + SM_A + ao + 8 * A_STRIDE + 16);
        const uint2* wrow = (const uint2*)(smem + SM_W) + kk * 512 + lane;
#pragma unroll
        for (int j = 0; j < 16; ++j) {
            const uint2 b = wrow[j * 32];
            mma_f16(acc[j], a0, a1, a2, a3, b.x, b.y);
        }
    }

    // epilogue: rows r0 = rowBase + wid*16 + g, r1 = r0 + 8; h stored fp16
    const int r0 = rowBase + wid * 16 + g;
    const int r1 = r0 + 8;
    float ps0[4] = {0, 0, 0, 0}, ps1[4] = {0, 0, 0, 0};
    float pd0[4] = {0, 0, 0, 0}, pd1[4] = {0, 0, 0, 0};
#pragma unroll
    for (int j = 0; j < 16; ++j) {
        const int col = j * 8 + t * 2;
        const int h = j >> 2;
        const float s0 = a_s[col], s1 = a_s[col + 1];
        const float d0 = a_d[col], d1 = a_d[col + 1];
        ps0[h] += acc[j][0] * s0 + acc[j][1] * s1;
        pd0[h] += acc[j][0] * d0 + acc[j][1] * d1;
        ps1[h] += acc[j][2] * s0 + acc[j][3] * s1;
        pd1[h] += acc[j][2] * d0 + acc[j][3] * d1;
        if (r0 < Nn) *(__half2*)(hout + (size_t)r0 * 128 + col) = __floats2half2_rn(acc[j][0], acc[j][1]);
        if (r1 < Nn) *(__half2*)(hout + (size_t)r1 * 128 + col) = __floats2half2_rn(acc[j][2], acc[j][3]);
    }
#pragma unroll
    for (int m = 1; m <= 2; m <<= 1) {
#pragma unroll
        for (int h = 0; h < 4; ++h) {
            ps0[h] += __shfl_xor_sync(0xffffffffu, ps0[h], m);
            ps1[h] += __shfl_xor_sync(0xffffffffu, ps1[h], m);
            pd0[h] += __shfl_xor_sync(0xffffffffu, pd0[h], m);
            pd1[h] += __shfl_xor_sync(0xffffffffu, pd1[h], m);
        }
    }
    if (t == 0) {
        if (r0 < Nn) {
            asout[r0] = make_float4(ps0[0], ps0[1], ps0[2], ps0[3]);
            adout[r0] = make_float4(pd0[0], pd0[1], pd0[2], pd0[3]);
        }
        if (r1 < Nn) {
            asout[r1] = make_float4(ps1[0], ps1[1], ps1[2], ps1[3]);
            adout[r1] = make_float4(pd1[0], pd1[1], pd1[2], pd1[3]);
        }
    }
}

// ---- fused GAT aggregation: one warp per dst node, fp16 h gather,
// 4-way pipelined. Output fp32 (out32) or fp16 (out16) - exactly one non-null.
__global__ __launch_bounds__(256)
void k_gat_agg(const __half* __restrict__ h, float4* __restrict__ out32,
               uint2* __restrict__ out16, const float* __restrict__ bias, int Nn) {
    __shared__ float wsm[8][32][4];
    __shared__ int   ssm[8][32];

    const int warp = (blockIdx.x * 256 + threadIdx.x) >> 5;
    const int lane = threadIdx.x & 31;
    const int w    = threadIdx.x >> 5;
    if (warp >= Nn) return;
    const int v = warp;
    const int head = lane >> 3;

    const float4 adv = g_ad[v];

    float4 acc;
    float  den;
    {
        const float4 asv = g_as[v];
        float4 we;
        we.x = __expf(lrelu(asv.x + adv.x));
        we.y = __expf(lrelu(asv.y + adv.y));
        we.z = __expf(lrelu(asv.z + adv.z));
        we.w = __expf(lrelu(asv.w + adv.w));
        const float wh = (head == 0) ? we.x : (head == 1) ? we.y : (head == 2) ? we.z : we.w;
        const uint2 hv = ((const uint2*)(h + (size_t)v * 128))[lane];
        const float2 p0 = __half22float2(*(const __half2*)&hv.x);
        const float2 p1 = __half22float2(*(const __half2*)&hv.y);
        acc = make_float4(p0.x * wh, p0.y * wh, p1.x * wh, p1.y * wh);
        den = wh;
    }

    const int beg = g_rowp[v];
    const int end = g_rowp[v + 1];
    for (int base = beg; base < end; base += 32) {
        int n = end - base; if (n > 32) n = 32;
        int sidx = 0;
        float4 we = make_float4(0.f, 0.f, 0.f, 0.f);
        if (lane < n) {
            sidx = g_csrc[base + lane];
            const float4 s = g_as[sidx];
            we.x = __expf(lrelu(s.x + adv.x));
            we.y = __expf(lrelu(s.y + adv.y));
            we.z = __expf(lrelu(s.z + adv.z));
            we.w = __expf(lrelu(s.w + adv.w));
        }
        ssm[w][lane] = sidx;
        *(float4*)&wsm[w][lane][0] = we;
        __syncwarp();

        int j = 0;
        for (; j + 4 <= n; j += 4) {
            const int   s0 = ssm[w][j],     s1 = ssm[w][j + 1];
            const int   s2 = ssm[w][j + 2], s3 = ssm[w][j + 3];
            const uint2 h0 = ((const uint2*)(h + (size_t)s0 * 128))[lane];
            const uint2 h1 = ((const uint2*)(h + (size_t)s1 * 128))[lane];
            const uint2 h2 = ((const uint2*)(h + (size_t)s2 * 128))[lane];
            const uint2 h3 = ((const uint2*)(h + (size_t)s3 * 128))[lane];
            const float w0 = wsm[w][j][head],     w1 = wsm[w][j + 1][head];
            const float w2 = wsm[w][j + 2][head], w3 = wsm[w][j + 3][head];
            float2 p;
            p = __half22float2(*(const __half2*)&h0.x); acc.x += w0 * p.x; acc.y += w0 * p.y;
            p = __half22float2(*(const __half2*)&h0.y); acc.z += w0 * p.x; acc.w += w0 * p.y;
            p = __half22float2(*(const __half2*)&h1.x); acc.x += w1 * p.x; acc.y += w1 * p.y;
            p = __half22float2(*(const __half2*)&h1.y); acc.z += w1 * p.x; acc.w += w1 * p.y;
            p = __half22float2(*(const __half2*)&h2.x); acc.x += w2 * p.x; acc.y += w2 * p.y;
            p = __half22float2(*(const __half2*)&h2.y); acc.z += w2 * p.x; acc.w += w2 * p.y;
            p = __half22float2(*(const __half2*)&h3.x); acc.x += w3 * p.x; acc.y += w3 * p.y;
            p = __half22float2(*(const __half2*)&h3.y); acc.z += w3 * p.x; acc.w += w3 * p.y;
            den += w0 + w1 + w2 + w3;
        }
        for (; j < n; ++j) {
            const int   sj = ssm[w][j];
            const float wj = wsm[w][j][head];
            const uint2 hv = ((const uint2*)(h + (size_t)sj * 128))[lane];
            const float2 p0 = __half22float2(*(const __half2*)&hv.x);
            const float2 p1 = __half22float2(*(const __half2*)&hv.y);
            acc.x += wj * p0.x; acc.y += wj * p0.y;
            acc.z += wj * p1.x; acc.w += wj * p1.y;
            den += wj;
        }
        __syncwarp();
    }

    const float inv = __fdividef(1.f, den);
    const float4 b4 = ((const float4*)bias)[lane];
    float4 o;
    o.x = fmaxf(acc.x * inv + b4.x, 0.f);
    o.y = fmaxf(acc.y * inv + b4.y, 0.f);
    o.z = fmaxf(acc.z * inv + b4.z, 0.f);
    o.w = fmaxf(acc.w * inv + b4.w, 0.f);
    if (out32) {
        out32[(size_t)v * 32 + lane] = o;
    } else {
        __half2 q0 = __floats2half2_rn(o.x, o.y);
        __half2 q1 = __floats2half2_rn(o.z, o.w);
        uint2 q;
        q.x = *(uint32_t*)&q0;
        q.y = *(uint32_t*)&q1;
        out16[(size_t)v * 32 + lane] = q;
    }
}

// ---------------- launch -----------------------------------------------------
extern "C" void kernel_launch(void* const* d_in, const int* in_sizes, int n_in,
                              void* d_out, int out_size) {
    const float* x   = (const float*)d_in[0];
    const void*  ei  = d_in[1];
    const float* W1  = (const float*)d_in[2];
    const float* as1 = (const float*)d_in[3];
    const float* ad1 = (const float*)d_in[4];
    const float* b1  = (const float*)d_in[5];
    const float* W2  = (const float*)d_in[6];
    const float* as2 = (const float*)d_in[7];
    const float* ad2 = (const float*)d_in[8];
    const float* b2  = (const float*)d_in[9];

    const int N  = in_sizes[0] / 128;
    const int E  = in_sizes[1] / 2;

    void* ph = nullptr;   cudaGetSymbolAddress(&ph,  g_hh);
    void* po = nullptr;   cudaGetSymbolAddress(&po,  g_o16);
    void* pas = nullptr;  cudaGetSymbolAddress(&pas, g_as);
    void* pad = nullptr;  cudaGetSymbolAddress(&pad, g_ad);
    void* pdeg = nullptr; cudaGetSymbolAddress(&pdeg, g_deg);

    const int ebl = (E + 255) / 256;
    const int abl = (N * 32 + 255) / 256;
    const int gbl = (N + 127) / 128;
    const int sbl = (N + SCAN_CHUNK - 1) / SCAN_CHUNK;

    cudaFuncSetAttribute(k_gemm_mma, cudaFuncAttributeMaxDynamicSharedMemorySize, SMEM_SZ);

    static cudaStream_t s2 = nullptr;
    static cudaEvent_t evFork = nullptr, evJoin = nullptr;
    if (!s2) {
        cudaStreamCreateWithFlags(&s2, cudaStreamNonBlocking);
        cudaEventCreateWithFlags(&evFork, cudaEventDisableTiming);
        cudaEventCreateWithFlags(&evJoin, cudaEventDisableTiming);
    }

    // ---- fork immediately: CSR build (incl. dtype detect) on s2 ----
    cudaEventRecord(evFork, 0);
    cudaStreamWaitEvent(s2, evFork, 0);

    cudaMemsetAsync(pdeg, 0, N * sizeof(int), s2);
    k_detect<<<1, 32, 0, s2>>>((const int*)ei);
    k_hist<<<ebl, 256, 0, s2>>>(ei, E);
    k_scan_fused<<<sbl, 1024, 0, s2>>>(N, sbl);
    k_scatter<<<ebl, 256, 0, s2>>>(ei, E);
    cudaEventRecord(evJoin, s2);

    // ---- main stream: layer-1 GEMM ----
    k_wprep<<<128, 256>>>(W1, W2);
    k_gemm_mma<<<gbl, 256, SMEM_SZ>>>(x, nullptr, 0, as1, ad1, (__half*)ph,
                                      (float4*)pas, (float4*)pad, N);

    // ---- join: aggregation needs both CSR and GEMM-1 ----
    cudaStreamWaitEvent(0, evJoin, 0);
    k_gat_agg<<<abl, 256>>>((const __half*)ph, nullptr, (uint2*)po, b1, N);

    // ---- layer 2 ----
    k_gemm_mma<<<gbl, 256, SMEM_SZ>>>(nullptr, (const __half*)po, 1, as2, ad2,
                                      (__half*)ph, (float4*)pas, (float4*)pad, N);
    k_gat_agg<<<abl, 256>>>((const __half*)ph, (float4*)d_out, nullptr, b2, N);
}